// round 10
// baseline (speedup 1.0000x reference)
#include <cuda_runtime.h>

#define H_DIM 10
#define N_DIM 100000
#define F_DIM 256
#define HID_DIM 512
#define C_DIM 47

// ---------------- scratch (device globals: no allocation allowed) ----------------
__device__ float g_right[(size_t)N_DIM * F_DIM];   // 102.4 MB
__device__ float g_x1[(size_t)N_DIM * HID_DIM];    // 204.8 MB  (h0 / y0 / y2)
__device__ float g_x2[(size_t)N_DIM * HID_DIM];    // 204.8 MB  (x2 / y1)
__device__ float g_x3[(size_t)N_DIM * HID_DIM];    // 204.8 MB  (x3)
__device__ float g_xout[(size_t)N_DIM * C_DIM];    // 18.8 MB

// ---------------- helpers ----------------
__device__ __forceinline__ float lrelu02(float x) { return x >= 0.f ? x : 0.2f * x; }
__device__ __forceinline__ float preluf(float x, float a) { return x >= 0.f ? x : a * x; }

__device__ __forceinline__ void ffma2(unsigned long long& acc,
                                      unsigned long long a,
                                      unsigned long long b) {
    asm("fma.rn.f32x2 %0, %1, %2, %0;" : "+l"(acc) : "l"(a), "l"(b));
}
__device__ __forceinline__ float ull_lo(unsigned long long u) {
    return __uint_as_float((unsigned)u);
}
__device__ __forceinline__ float ull_hi(unsigned long long u) {
    return __uint_as_float((unsigned)(u >> 32));
}
__device__ __forceinline__ unsigned long long dupf(float x) {
    unsigned u = __float_as_uint(x);
    return ((unsigned long long)u << 32) | u;
}

// ---------------- fused attention: one pass over features ----------------
__global__ __launch_bounds__(128)
void attn_kernel(const float* __restrict__ feat,
                 const float* __restrict__ wa,
                 const float* __restrict__ ba_p,
                 float* __restrict__ right)
{
    const int warp = threadIdx.x >> 5;
    const int lane = threadIdx.x & 31;
    const int n = blockIdx.x * 4 + warp;
    if (n >= N_DIM) return;

    const float4* wa4 = reinterpret_cast<const float4*>(wa);
    const float4 wl_a = wa4[lane];
    const float4 wl_b = wa4[32 + lane];
    const float4 wr_a = wa4[64 + lane];
    const float4 wr_b = wa4[96 + lane];
    const float ba = *ba_p;

    float4 fa[H_DIM], fb[H_DIM];
    float xl[H_DIM], xr[H_DIM];

#pragma unroll
    for (int h = 0; h < H_DIM; ++h) {
        const float4* f4 = reinterpret_cast<const float4*>(
            feat + ((size_t)h * N_DIM + (size_t)n) * F_DIM);
        fa[h] = f4[lane];
        fb[h] = f4[32 + lane];
        float dl = fa[h].x * wl_a.x + fa[h].y * wl_a.y + fa[h].z * wl_a.z + fa[h].w * wl_a.w
                 + fb[h].x * wl_b.x + fb[h].y * wl_b.y + fb[h].z * wl_b.z + fb[h].w * wl_b.w;
        float dr = fa[h].x * wr_a.x + fa[h].y * wr_a.y + fa[h].z * wr_a.z + fa[h].w * wr_a.w
                 + fb[h].x * wr_b.x + fb[h].y * wr_b.y + fb[h].z * wr_b.z + fb[h].w * wr_b.w;
#pragma unroll
        for (int off = 16; off; off >>= 1) {
            dl += __shfl_xor_sync(0xffffffffu, dl, off);
            dr += __shfl_xor_sync(0xffffffffu, dr, off);
        }
        xl[h] = dl;
        xr[h] = dr;
    }

    float sc[H_DIM];
    sc[0] = lrelu02(xl[0] + xr[0] + ba);
#pragma unroll
    for (int i = 1; i < H_DIM; ++i) {
        float mx = sc[0];
#pragma unroll
        for (int j = 1; j < i; ++j) mx = fmaxf(mx, sc[j]);
        float s = 0.f, accv = 0.f;
#pragma unroll
        for (int j = 0; j < i; ++j) {
            float e = __expf(sc[j] - mx);
            s += e;
            accv += e * xl[j];
        }
        sc[i] = lrelu02(accv / s + xr[i] + ba);
    }

    float mx = sc[0];
#pragma unroll
    for (int j = 1; j < H_DIM; ++j) mx = fmaxf(mx, sc[j]);
    float s = 0.f;
    float4 ra = make_float4(0.f, 0.f, 0.f, 0.f);
    float4 rb = make_float4(0.f, 0.f, 0.f, 0.f);
#pragma unroll
    for (int h = 0; h < H_DIM; ++h) {
        float e = __expf(sc[h] - mx);
        s += e;
        ra.x += e * fa[h].x; ra.y += e * fa[h].y; ra.z += e * fa[h].z; ra.w += e * fa[h].w;
        rb.x += e * fb[h].x; rb.y += e * fb[h].y; rb.z += e * fb[h].z; rb.w += e * fb[h].w;
    }
    float inv = 1.f / s;
    ra.x *= inv; ra.y *= inv; ra.z *= inv; ra.w *= inv;
    rb.x *= inv; rb.y *= inv; rb.z *= inv; rb.w *= inv;

    float4* out4 = reinterpret_cast<float4*>(right + (size_t)n * F_DIM);
    out4[lane] = ra;
    out4[32 + lane] = rb;
}

// ---------------- fused GEMM (fp32 SIMT, f32x2 FMA, A duplicated in smem) ----------
// C[m,n] = epi( in(A)[m,:] @ W[:,n] )
// IN_MODE:  0 = A        1 = prelu(A,a_in)       2 = 0.5*(prelu(A,a_in)+H0)
// RES_MODE: 0 = none     1 = +R[m,n]             2 = +prelu(R[m,n],a_ep)
// HAS_BIAS: +bias[n];  EPI_PRELU: prelu(result,a_ep) at the end
template<int IN_MODE, int HAS_BIAS, int EPI_PRELU, int RES_MODE>
__global__ __launch_bounds__(256, 2)   // force <=128 regs -> 2 CTAs/SM -> 4 warps/SMSP
void gemm_k(const float* __restrict__ A, const float* __restrict__ Hh,
            const float* __restrict__ W, const float* __restrict__ bias,
            const float* __restrict__ R, float* __restrict__ C,
            int M, int N, int K,
            const float* __restrict__ a_in_p, const float* __restrict__ a_ep_p)
{
    constexpr int BM = 128, BN = 128, BK = 8;
    // A stored duplicated along m (each value twice) -> f32x2 operand (m,m).
    // A reads are warp-broadcast, so duplication is crossbar-free.
    __shared__ __align__(16) float As[2][BK][2 * BM + 8];
    __shared__ __align__(16) float Bs[2][BK][BN];

    const int tid = threadIdx.x;
    const int bm = blockIdx.y * BM;
    const int bn = blockIdx.x * BN;

    float a_in = 0.f, a_ep = 0.f;
    if constexpr (IN_MODE >= 1) a_in = *a_in_p;
    if constexpr (EPI_PRELU || RES_MODE == 2) a_ep = *a_ep_p;

    // global-load assignments (one float4 of A, one float4 of B per thread per tile)
    const int ar  = tid >> 1;          // A row within tile (0..127)
    const int ak  = (tid & 1) << 2;    // A k-offset (0 or 4)
    const int bk  = tid >> 5;          // B k (0..7)
    const int bn0 = (tid & 31) << 2;   // B col offset (0..124)

    const bool kvec = (K & 3) == 0;
    const bool nvec = (N & 3) == 0;

    float4 aR, bR;

    auto loadAB = [&](int kt) {
        {
            int row = bm + ar;
            int k = kt + ak;
            float4 v  = make_float4(0.f, 0.f, 0.f, 0.f);
            float4 hv = make_float4(0.f, 0.f, 0.f, 0.f);
            if (row < M && k < K) {
                const float* p = A + (size_t)row * K + k;
                if (kvec) {
                    v = *reinterpret_cast<const float4*>(p);
                } else {
                    v.x = p[0];
                    if (k + 1 < K) v.y = p[1];
                    if (k + 2 < K) v.z = p[2];
                    if (k + 3 < K) v.w = p[3];
                }
                if constexpr (IN_MODE == 2) {
                    const float* q = Hh + (size_t)row * K + k;
                    if (kvec) {
                        hv = *reinterpret_cast<const float4*>(q);
                    } else {
                        hv.x = q[0];
                        if (k + 1 < K) hv.y = q[1];
                        if (k + 2 < K) hv.z = q[2];
                        if (k + 3 < K) hv.w = q[3];
                    }
                }
            }
            if constexpr (IN_MODE == 1) {
                v.x = preluf(v.x, a_in); v.y = preluf(v.y, a_in);
                v.z = preluf(v.z, a_in); v.w = preluf(v.w, a_in);
            } else if constexpr (IN_MODE == 2) {
                v.x = 0.5f * (preluf(v.x, a_in) + hv.x);
                v.y = 0.5f * (preluf(v.y, a_in) + hv.y);
                v.z = 0.5f * (preluf(v.z, a_in) + hv.z);
                v.w = 0.5f * (preluf(v.w, a_in) + hv.w);
            }
            aR = v;
        }
        {
            int k = kt + bk;
            int n = bn + bn0;
            float4 v = make_float4(0.f, 0.f, 0.f, 0.f);
            if (k < K && n < N) {
                const float* p = W + (size_t)k * N + n;
                if (nvec) {
                    v = *reinterpret_cast<const float4*>(p);
                } else {
                    v.x = p[0];
                    if (n + 1 < N) v.y = p[1];
                    if (n + 2 < N) v.z = p[2];
                    if (n + 3 < N) v.w = p[3];
                }
            }
            bR = v;
        }
    };

    auto stage = [&](int buf) {
        // A duplicated: row k, ull slot ar holds (v, v)
        reinterpret_cast<unsigned long long*>(As[buf][ak + 0])[ar] = dupf(aR.x);
        reinterpret_cast<unsigned long long*>(As[buf][ak + 1])[ar] = dupf(aR.y);
        reinterpret_cast<unsigned long long*>(As[buf][ak + 2])[ar] = dupf(aR.z);
        reinterpret_cast<unsigned long long*>(As[buf][ak + 3])[ar] = dupf(aR.w);
        *reinterpret_cast<float4*>(&Bs[buf][bk][bn0]) = bR;
    };

    const int ty = tid >> 4;   // 0..15 -> rows bm + ty*8 .. +7
    const int tx = tid & 15;   // cols: bn + tx*4 (+0..3) and bn + 64 + tx*4 (+0..3)

    unsigned long long acc[8][4];
#pragma unroll
    for (int i = 0; i < 8; ++i)
#pragma unroll
        for (int j = 0; j < 4; ++j) acc[i][j] = 0ull;

    const int tiles = (K + BK - 1) / BK;
    loadAB(0);
    stage(0);
    __syncthreads();

    int buf = 0;
    for (int t = 0; t < tiles; ++t) {
        const bool more = (t + 1 < tiles);
        if (more) loadAB((t + 1) * BK);
#pragma unroll
        for (int k = 0; k < BK; ++k) {
            const ulonglong2* ap =
                reinterpret_cast<const ulonglong2*>(&As[buf][k][ty << 4]);
            ulonglong2 a01 = ap[0], a23 = ap[1], a45 = ap[2], a67 = ap[3];
            ulonglong2 b01 = *reinterpret_cast<const ulonglong2*>(&Bs[buf][k][tx << 2]);
            ulonglong2 b23 = *reinterpret_cast<const ulonglong2*>(&Bs[buf][k][(tx << 2) + 64]);
            unsigned long long av[8] = {a01.x, a01.y, a23.x, a23.y,
                                        a45.x, a45.y, a67.x, a67.y};
#pragma unroll
            for (int i = 0; i < 8; ++i) {
                ffma2(acc[i][0], av[i], b01.x);
                ffma2(acc[i][1], av[i], b01.y);
                ffma2(acc[i][2], av[i], b23.x);
                ffma2(acc[i][3], av[i], b23.y);
            }
        }
        if (more) {
            stage(buf ^ 1);
            __syncthreads();
            buf ^= 1;
        }
    }

    // ---------------- epilogue ----------------
#pragma unroll
    for (int i = 0; i < 8; ++i) {
        const int m = bm + (ty << 3) + i;
        if (m >= M) continue;
#pragma unroll
        for (int g = 0; g < 2; ++g) {
            const int n0 = bn + (g << 6) + (tx << 2);
            float f0 = ull_lo(acc[i][2 * g]);
            float f1 = ull_hi(acc[i][2 * g]);
            float f2 = ull_lo(acc[i][2 * g + 1]);
            float f3 = ull_hi(acc[i][2 * g + 1]);
            if (nvec && n0 + 3 < N) {
                if constexpr (HAS_BIAS) {
                    float4 bv = *reinterpret_cast<const float4*>(bias + n0);
                    f0 += bv.x; f1 += bv.y; f2 += bv.z; f3 += bv.w;
                }
                if constexpr (RES_MODE == 1) {
                    float4 rv = *reinterpret_cast<const float4*>(R + (size_t)m * N + n0);
                    f0 += rv.x; f1 += rv.y; f2 += rv.z; f3 += rv.w;
                } else if constexpr (RES_MODE == 2) {
                    float4 rv = *reinterpret_cast<const float4*>(R + (size_t)m * N + n0);
                    f0 += preluf(rv.x, a_ep); f1 += preluf(rv.y, a_ep);
                    f2 += preluf(rv.z, a_ep); f3 += preluf(rv.w, a_ep);
                }
                if constexpr (EPI_PRELU) {
                    f0 = preluf(f0, a_ep); f1 = preluf(f1, a_ep);
                    f2 = preluf(f2, a_ep); f3 = preluf(f3, a_ep);
                }
                *reinterpret_cast<float4*>(C + (size_t)m * N + n0) =
                    make_float4(f0, f1, f2, f3);
            } else {
                float f[4] = {f0, f1, f2, f3};
#pragma unroll
                for (int j = 0; j < 4; ++j) {
                    const int n = n0 + j;
                    if (n < N) {
                        float v = f[j];
                        if constexpr (HAS_BIAS) v += bias[n];
                        if constexpr (RES_MODE == 1) v += R[(size_t)m * N + n];
                        if constexpr (RES_MODE == 2) v += preluf(R[(size_t)m * N + n], a_ep);
                        if constexpr (EPI_PRELU) v = preluf(v, a_ep);
                        C[(size_t)m * N + n] = v;
                    }
                }
            }
        }
    }
}

// ---------------- launch ----------------
extern "C" void kernel_launch(void* const* d_in, const int* in_sizes, int n_in,
                              void* d_out, int out_size)
{
    (void)in_sizes; (void)n_in; (void)out_size;

    const float* features  = (const float*)d_in[0];
    const float* label_emb = (const float*)d_in[1];
    const float* wa        = (const float*)d_in[2];
    const float* ba        = (const float*)d_in[3];
    const float* w0        = (const float*)d_in[4];
    const float* b0        = (const float*)d_in[5];
    const float* wg1       = (const float*)d_in[6];
    const float* wg2       = (const float*)d_in[7];
    const float* w_last    = (const float*)d_in[8];
    const float* b_last    = (const float*)d_in[9];
    const float* a_out     = (const float*)d_in[10];
    const float* wl0       = (const float*)d_in[11];
    const float* bl0       = (const float*)d_in[12];
    const float* wl1       = (const float*)d_in[13];
    const float* bl1       = (const float*)d_in[14];
    const float* wl2       = (const float*)d_in[15];
    const float* bl2       = (const float*)d_in[16];
    const float* wl3       = (const float*)d_in[17];
    const float* bl3       = (const float*)d_in[18];
    const float* a_lab     = (const float*)d_in[19];

    float *right, *x1, *x2, *x3, *xout;
    cudaGetSymbolAddress((void**)&right, g_right);
    cudaGetSymbolAddress((void**)&x1, g_x1);
    cudaGetSymbolAddress((void**)&x2, g_x2);
    cudaGetSymbolAddress((void**)&x3, g_x3);
    cudaGetSymbolAddress((void**)&xout, g_xout);

    // 1) fused attention -> right [N, F]
    attn_kernel<<<(N_DIM + 3) / 4, 128>>>(features, wa, ba, right);

    auto grid = [](int M, int N) { return dim3((unsigned)((N + 127) / 128), (unsigned)((M + 127) / 128)); };
    dim3 blk(256);

    // 2) x1 = right @ w0 + b0           (h0)
    gemm_k<0, 1, 0, 0><<<grid(N_DIM, HID_DIM), blk>>>(
        right, nullptr, w0, b0, nullptr, x1, N_DIM, HID_DIM, F_DIM, nullptr, nullptr);

    // 3) x2 = support(x1, x1) @ wg1 + prelu(x1)
    gemm_k<2, 0, 0, 2><<<grid(N_DIM, HID_DIM), blk>>>(
        x1, x1, wg1, nullptr, x1, x2, N_DIM, HID_DIM, HID_DIM, a_out, a_out);

    // 4) x3 = support(x2, x1) @ wg2 + prelu(x2)
    gemm_k<2, 0, 0, 2><<<grid(N_DIM, HID_DIM), blk>>>(
        x2, x1, wg2, nullptr, x2, x3, N_DIM, HID_DIM, HID_DIM, a_out, a_out);

    // 5) xout = prelu(x3) @ w_last + b_last
    gemm_k<1, 1, 0, 0><<<grid(N_DIM, C_DIM), blk>>>(
        x3, nullptr, w_last, b_last, nullptr, xout, N_DIM, C_DIM, HID_DIM, a_out, nullptr);

    // 6) y0 = prelu(label_emb @ wl0 + bl0)   -> x1
    gemm_k<0, 1, 1, 0><<<grid(N_DIM, HID_DIM), blk>>>(
        label_emb, nullptr, wl0, bl0, nullptr, x1, N_DIM, HID_DIM, C_DIM, nullptr, a_lab);

    // 7) y1 = prelu(y0 @ wl1 + bl1)          -> x2
    gemm_k<0, 1, 1, 0><<<grid(N_DIM, HID_DIM), blk>>>(
        x1, nullptr, wl1, bl1, nullptr, x2, N_DIM, HID_DIM, HID_DIM, nullptr, a_lab);

    // 8) y2 = prelu(y1 @ wl2 + bl2)          -> x1
    gemm_k<0, 1, 1, 0><<<grid(N_DIM, HID_DIM), blk>>>(
        x2, nullptr, wl2, bl2, nullptr, x1, N_DIM, HID_DIM, HID_DIM, nullptr, a_lab);

    // 9) out = y2 @ wl3 + bl3 + xout         -> d_out
    gemm_k<0, 1, 0, 1><<<grid(N_DIM, C_DIM), blk>>>(
        x1, nullptr, wl3, bl3, xout, (float*)d_out, N_DIM, C_DIM, HID_DIM, nullptr, nullptr);
}

// round 13
// speedup vs baseline: 2.4226x; 2.4226x over previous
#include <cuda_runtime.h>
#include <cuda_bf16.h>
#include <cstdint>

#define H_DIM 10
#define N_DIM 100000
#define F_DIM 256
#define HID_DIM 512
#define C_DIM 47

// ---------------- scratch (device globals: no allocation allowed) ----------------
__device__ float g_right[(size_t)N_DIM * F_DIM];
__device__ float g_x1[(size_t)N_DIM * HID_DIM];
__device__ float g_x2[(size_t)N_DIM * HID_DIM];
__device__ float g_x3[(size_t)N_DIM * HID_DIM];
__device__ float g_xout[(size_t)N_DIM * C_DIM];

// split/transposed weights (bf16 hi/lo, K-major rows of W^T)
__device__ __nv_bfloat16 g_w0t_hi[512 * 256];
__device__ __nv_bfloat16 g_w0t_lo[512 * 256];
__device__ __nv_bfloat16 g_wg1t_hi[512 * 512];
__device__ __nv_bfloat16 g_wg1t_lo[512 * 512];
__device__ __nv_bfloat16 g_wg2t_hi[512 * 512];
__device__ __nv_bfloat16 g_wg2t_lo[512 * 512];
__device__ __nv_bfloat16 g_wl1t_hi[512 * 512];
__device__ __nv_bfloat16 g_wl1t_lo[512 * 512];
__device__ __nv_bfloat16 g_wl2t_hi[512 * 512];
__device__ __nv_bfloat16 g_wl2t_lo[512 * 512];

// ---------------- helpers ----------------
__device__ __forceinline__ float lrelu02(float x) { return x >= 0.f ? x : 0.2f * x; }
__device__ __forceinline__ float preluf(float x, float a) { return x >= 0.f ? x : a * x; }

__device__ __forceinline__ void ffma2(unsigned long long& acc,
                                      unsigned long long a,
                                      unsigned long long b) {
    asm("fma.rn.f32x2 %0, %1, %2, %0;" : "+l"(acc) : "l"(a), "l"(b));
}
__device__ __forceinline__ float ull_lo(unsigned long long u) { return __uint_as_float((unsigned)u); }
__device__ __forceinline__ float ull_hi(unsigned long long u) { return __uint_as_float((unsigned)(u >> 32)); }
__device__ __forceinline__ unsigned long long dupf(float x) {
    unsigned u = __float_as_uint(x);
    return ((unsigned long long)u << 32) | u;
}
__device__ __forceinline__ uint32_t pack_bf2(__nv_bfloat16 lo16, __nv_bfloat16 hi16) {
    return ((uint32_t)__bfloat16_as_ushort(hi16) << 16) | __bfloat16_as_ushort(lo16);
}

// mma.sync bf16 m16n8k16 (baseline PTX: compiles for compute_103, runs on tensor cores)
__device__ __forceinline__ void mma16816(float* c, const uint32_t* a, const uint32_t* b) {
    asm volatile("mma.sync.aligned.m16n8k16.row.col.f32.bf16.bf16.f32 "
                 "{%0,%1,%2,%3}, {%4,%5,%6,%7}, {%8,%9}, {%0,%1,%2,%3};"
                 : "+f"(c[0]), "+f"(c[1]), "+f"(c[2]), "+f"(c[3])
                 : "r"(a[0]), "r"(a[1]), "r"(a[2]), "r"(a[3]), "r"(b[0]), "r"(b[1]));
}

// ---------------- fused attention: one pass over features ----------------
__global__ __launch_bounds__(128)
void attn_kernel(const float* __restrict__ feat, const float* __restrict__ wa,
                 const float* __restrict__ ba_p, float* __restrict__ right)
{
    const int warp = threadIdx.x >> 5;
    const int lane = threadIdx.x & 31;
    const int n = blockIdx.x * 4 + warp;
    if (n >= N_DIM) return;

    const float4* wa4 = reinterpret_cast<const float4*>(wa);
    const float4 wl_a = wa4[lane];
    const float4 wl_b = wa4[32 + lane];
    const float4 wr_a = wa4[64 + lane];
    const float4 wr_b = wa4[96 + lane];
    const float ba = *ba_p;

    float4 fa[H_DIM], fb[H_DIM];
    float xl[H_DIM], xr[H_DIM];

#pragma unroll
    for (int h = 0; h < H_DIM; ++h) {
        const float4* f4 = reinterpret_cast<const float4*>(
            feat + ((size_t)h * N_DIM + (size_t)n) * F_DIM);
        fa[h] = f4[lane];
        fb[h] = f4[32 + lane];
        float dl = fa[h].x * wl_a.x + fa[h].y * wl_a.y + fa[h].z * wl_a.z + fa[h].w * wl_a.w
                 + fb[h].x * wl_b.x + fb[h].y * wl_b.y + fb[h].z * wl_b.z + fb[h].w * wl_b.w;
        float dr = fa[h].x * wr_a.x + fa[h].y * wr_a.y + fa[h].z * wr_a.z + fa[h].w * wr_a.w
                 + fb[h].x * wr_b.x + fb[h].y * wr_b.y + fb[h].z * wr_b.z + fb[h].w * wr_b.w;
#pragma unroll
        for (int off = 16; off; off >>= 1) {
            dl += __shfl_xor_sync(0xffffffffu, dl, off);
            dr += __shfl_xor_sync(0xffffffffu, dr, off);
        }
        xl[h] = dl;
        xr[h] = dr;
    }

    float sc[H_DIM];
    sc[0] = lrelu02(xl[0] + xr[0] + ba);
#pragma unroll
    for (int i = 1; i < H_DIM; ++i) {
        float mx = sc[0];
#pragma unroll
        for (int j = 1; j < i; ++j) mx = fmaxf(mx, sc[j]);
        float s = 0.f, accv = 0.f;
#pragma unroll
        for (int j = 0; j < i; ++j) {
            float e = __expf(sc[j] - mx);
            s += e;
            accv += e * xl[j];
        }
        sc[i] = lrelu02(accv / s + xr[i] + ba);
    }

    float mx = sc[0];
#pragma unroll
    for (int j = 1; j < H_DIM; ++j) mx = fmaxf(mx, sc[j]);
    float s = 0.f;
    float4 ra = make_float4(0.f, 0.f, 0.f, 0.f);
    float4 rb = make_float4(0.f, 0.f, 0.f, 0.f);
#pragma unroll
    for (int h = 0; h < H_DIM; ++h) {
        float e = __expf(sc[h] - mx);
        s += e;
        ra.x += e * fa[h].x; ra.y += e * fa[h].y; ra.z += e * fa[h].z; ra.w += e * fa[h].w;
        rb.x += e * fb[h].x; rb.y += e * fb[h].y; rb.z += e * fb[h].z; rb.w += e * fb[h].w;
    }
    float inv = 1.f / s;
    ra.x *= inv; ra.y *= inv; ra.z *= inv; ra.w *= inv;
    rb.x *= inv; rb.y *= inv; rb.z *= inv; rb.w *= inv;

    float4* out4 = reinterpret_cast<float4*>(right + (size_t)n * F_DIM);
    out4[lane] = ra;
    out4[32 + lane] = rb;
}

// ---------------- weight transpose + bf16 split prep ----------------
__global__ void split_wt_kernel(const float* __restrict__ w,
                                __nv_bfloat16* __restrict__ hi,
                                __nv_bfloat16* __restrict__ lo,
                                int K, int N)
{
    int idx = blockIdx.x * 256 + threadIdx.x;
    if (idx >= K * N) return;
    int k = idx / N;
    int n = idx - k * N;
    float v = w[idx];
    __nv_bfloat16 h = __float2bfloat16(v);
    float rem = v - __bfloat162float(h);
    hi[(size_t)n * K + k] = h;
    lo[(size_t)n * K + k] = __float2bfloat16(rem);
}

// ---------------- HMMA split-bf16 GEMM (mma.sync m16n8k16) ----------------
// CTA 256 thr / 8 warps, tile 128m x 64n, BK=32. Warp tile 32m x 32n.
// W pre-transposed/split (Whi/Wlo [N,K] K-major). N % 64 == 0, K % 32 == 0.
static constexpr int HM_LDA = 40;                       // bf16 per smem row (32 + pad)
static constexpr int HM_ASZ = 128 * HM_LDA * 2;         // 10240 B
static constexpr int HM_BSZ = 64 * HM_LDA * 2;          // 5120 B
static constexpr int HM_AHI = 0;
static constexpr int HM_ALO = HM_ASZ;
static constexpr int HM_BHI = 2 * HM_ASZ;
static constexpr int HM_BLO = 2 * HM_ASZ + HM_BSZ;
static constexpr int HM_BUF = 2 * HM_ASZ + 2 * HM_BSZ;  // 30720 B
static constexpr int HM_SMEM = 2 * HM_BUF;              // 61440 B

template<int IN_MODE, int HAS_BIAS, int EPI_PRELU, int RES_MODE>
__global__ __launch_bounds__(256)
void hmma_k(const float* __restrict__ A, const float* __restrict__ Hh,
            const __nv_bfloat16* __restrict__ Whi, const __nv_bfloat16* __restrict__ Wlo,
            const float* __restrict__ bias, const float* __restrict__ R,
            float* __restrict__ C, int M, int N, int K,
            const float* __restrict__ a_in_p, const float* __restrict__ a_ep_p)
{
    extern __shared__ char sm[];
    const int tid = threadIdx.x;
    const int lane = tid & 31;
    const int g  = lane >> 2;
    const int tg = lane & 3;
    const int w  = tid >> 5;
    const int mw = w & 3;      // 0..3  (32-row band)
    const int nw = w >> 2;     // 0..1  (32-col band)
    const int bm = blockIdx.y * 128;
    const int bn = blockIdx.x * 64;

    float a_in = 0.f, a_ep = 0.f;
    if constexpr (IN_MODE == 2) a_in = *a_in_p;
    if constexpr (EPI_PRELU || RES_MODE == 2) a_ep = *a_ep_p;

    // ---- staging assignment ----
    const int ar  = tid >> 1;          // A row 0..127
    const int akh = (tid & 1) * 16;    // A k offset 0/16
    const int brn = tid >> 2;          // B n-row 0..63
    const int bkc = (tid & 3) * 8;     // B k offset 0/8/16/24
    const int arow_g = bm + ar;
    const bool avalid = arow_g < M;

    float aregs[16];
    uint4 bhr, blr;

    auto load_regs = [&](int c) {
        if (avalid) {
            const float4* ap = reinterpret_cast<const float4*>(A + (size_t)arow_g * K + c * 32 + akh);
#pragma unroll
            for (int i = 0; i < 4; ++i) {
                float4 v = ap[i];
                if constexpr (IN_MODE == 2) {
                    const float4* hp = reinterpret_cast<const float4*>(Hh + (size_t)arow_g * K + c * 32 + akh);
                    float4 h = hp[i];
                    v.x = 0.5f * (preluf(v.x, a_in) + h.x);
                    v.y = 0.5f * (preluf(v.y, a_in) + h.y);
                    v.z = 0.5f * (preluf(v.z, a_in) + h.z);
                    v.w = 0.5f * (preluf(v.w, a_in) + h.w);
                } else if constexpr (IN_MODE == 1) {
                    v.x = preluf(v.x, a_in); v.y = preluf(v.y, a_in);
                    v.z = preluf(v.z, a_in); v.w = preluf(v.w, a_in);
                }
                aregs[4 * i + 0] = v.x; aregs[4 * i + 1] = v.y;
                aregs[4 * i + 2] = v.z; aregs[4 * i + 3] = v.w;
            }
        } else {
#pragma unroll
            for (int i = 0; i < 16; ++i) aregs[i] = 0.f;
        }
        bhr = *reinterpret_cast<const uint4*>(Whi + (size_t)(bn + brn) * K + c * 32 + bkc);
        blr = *reinterpret_cast<const uint4*>(Wlo + (size_t)(bn + brn) * K + c * 32 + bkc);
    };

    auto store_stage = [&](int buf) {
        char* base = sm + buf * HM_BUF;
        uint32_t hw[8], lw[8];
#pragma unroll
        for (int q = 0; q < 8; ++q) {
            __nv_bfloat16 h0 = __float2bfloat16(aregs[2 * q]);
            __nv_bfloat16 h1 = __float2bfloat16(aregs[2 * q + 1]);
            float r0 = aregs[2 * q] - __bfloat162float(h0);
            float r1 = aregs[2 * q + 1] - __bfloat162float(h1);
            hw[q] = pack_bf2(h0, h1);
            lw[q] = pack_bf2(__float2bfloat16(r0), __float2bfloat16(r1));
        }
        const int aoff = ar * (HM_LDA * 2) + akh * 2;   // bytes
        *reinterpret_cast<uint4*>(base + HM_AHI + aoff)      = make_uint4(hw[0], hw[1], hw[2], hw[3]);
        *reinterpret_cast<uint4*>(base + HM_AHI + aoff + 16) = make_uint4(hw[4], hw[5], hw[6], hw[7]);
        *reinterpret_cast<uint4*>(base + HM_ALO + aoff)      = make_uint4(lw[0], lw[1], lw[2], lw[3]);
        *reinterpret_cast<uint4*>(base + HM_ALO + aoff + 16) = make_uint4(lw[4], lw[5], lw[6], lw[7]);
        const int boff = brn * (HM_LDA * 2) + bkc * 2;
        *reinterpret_cast<uint4*>(base + HM_BHI + boff) = bhr;
        *reinterpret_cast<uint4*>(base + HM_BLO + boff) = blr;
    };

    float c[2][4][4];
#pragma unroll
    for (int m = 0; m < 2; ++m)
#pragma unroll
        for (int j = 0; j < 4; ++j)
#pragma unroll
            for (int q = 0; q < 4; ++q) c[m][j][q] = 0.f;

    const int chunks = K / 32;
    load_regs(0);
    store_stage(0);
    __syncthreads();

    int buf = 0;
    for (int t = 0; t < chunks; ++t) {
        const bool more = (t + 1 < chunks);
        if (more) load_regs(t + 1);

        const char* base = sm + buf * HM_BUF;
        const char* pAhi = base + HM_AHI;
        const char* pAlo = base + HM_ALO;
        const char* pBhi = base + HM_BHI;
        const char* pBlo = base + HM_BLO;

#pragma unroll
        for (int ko = 0; ko < 32; ko += 16) {
            // B fragments for all 4 n-subtiles
            uint32_t bh[4][2], bl[4][2];
#pragma unroll
            for (int j = 0; j < 4; ++j) {
                const int nr = nw * 32 + j * 8 + g;
                const int o0 = nr * (HM_LDA * 2) + (ko + 2 * tg) * 2;
                const int o1 = nr * (HM_LDA * 2) + (ko + 8 + 2 * tg) * 2;
                bh[j][0] = *reinterpret_cast<const uint32_t*>(pBhi + o0);
                bh[j][1] = *reinterpret_cast<const uint32_t*>(pBhi + o1);
                bl[j][0] = *reinterpret_cast<const uint32_t*>(pBlo + o0);
                bl[j][1] = *reinterpret_cast<const uint32_t*>(pBlo + o1);
            }
#pragma unroll
            for (int m = 0; m < 2; ++m) {
                const int r0 = mw * 32 + m * 16 + g;
                const int r1 = r0 + 8;
                const int c0 = (ko + 2 * tg) * 2;
                const int c1 = (ko + 8 + 2 * tg) * 2;
                uint32_t ah[4], al[4];
                ah[0] = *reinterpret_cast<const uint32_t*>(pAhi + r0 * (HM_LDA * 2) + c0);
                ah[1] = *reinterpret_cast<const uint32_t*>(pAhi + r1 * (HM_LDA * 2) + c0);
                ah[2] = *reinterpret_cast<const uint32_t*>(pAhi + r0 * (HM_LDA * 2) + c1);
                ah[3] = *reinterpret_cast<const uint32_t*>(pAhi + r1 * (HM_LDA * 2) + c1);
                al[0] = *reinterpret_cast<const uint32_t*>(pAlo + r0 * (HM_LDA * 2) + c0);
                al[1] = *reinterpret_cast<const uint32_t*>(pAlo + r1 * (HM_LDA * 2) + c0);
                al[2] = *reinterpret_cast<const uint32_t*>(pAlo + r0 * (HM_LDA * 2) + c1);
                al[3] = *reinterpret_cast<const uint32_t*>(pAlo + r1 * (HM_LDA * 2) + c1);
#pragma unroll
                for (int j = 0; j < 4; ++j) {
                    mma16816(c[m][j], ah, bh[j]);   // hi*hi
                    mma16816(c[m][j], ah, bl[j]);   // hi*lo
                    mma16816(c[m][j], al, bh[j]);   // lo*hi
                }
            }
        }

        if (more) {
            store_stage(buf ^ 1);
            __syncthreads();
            buf ^= 1;
        }
    }

    // ---- epilogue ----
#pragma unroll
    for (int m = 0; m < 2; ++m) {
        const int r0g = bm + mw * 32 + m * 16 + g;
        const int r1g = r0g + 8;
#pragma unroll
        for (int j = 0; j < 4; ++j) {
            const int col = bn + nw * 32 + j * 8 + 2 * tg;
            float f0 = c[m][j][0], f1 = c[m][j][1];
            float f2 = c[m][j][2], f3 = c[m][j][3];
            if constexpr (HAS_BIAS) {
                float2 bv = *reinterpret_cast<const float2*>(bias + col);
                f0 += bv.x; f1 += bv.y;
                f2 += bv.x; f3 += bv.y;
            }
            if (r0g < M) {
                float g0 = f0, g1 = f1;
                if constexpr (RES_MODE == 2) {
                    float2 rv = *reinterpret_cast<const float2*>(R + (size_t)r0g * N + col);
                    g0 += preluf(rv.x, a_ep); g1 += preluf(rv.y, a_ep);
                }
                if constexpr (EPI_PRELU) { g0 = preluf(g0, a_ep); g1 = preluf(g1, a_ep); }
                *reinterpret_cast<float2*>(C + (size_t)r0g * N + col) = make_float2(g0, g1);
            }
            if (r1g < M) {
                float g2 = f2, g3 = f3;
                if constexpr (RES_MODE == 2) {
                    float2 rv = *reinterpret_cast<const float2*>(R + (size_t)r1g * N + col);
                    g2 += preluf(rv.x, a_ep); g3 += preluf(rv.y, a_ep);
                }
                if constexpr (EPI_PRELU) { g2 = preluf(g2, a_ep); g3 = preluf(g3, a_ep); }
                *reinterpret_cast<float2*>(C + (size_t)r1g * N + col) = make_float2(g2, g3);
            }
        }
    }
}

// ---------------- fp32 SIMT GEMM (small-N / small-K steps) ----------------
template<int IN_MODE, int HAS_BIAS, int EPI_PRELU, int RES_MODE>
__global__ __launch_bounds__(256, 2)
void gemm_k(const float* __restrict__ A, const float* __restrict__ Hh,
            const float* __restrict__ W, const float* __restrict__ bias,
            const float* __restrict__ R, float* __restrict__ C,
            int M, int N, int K,
            const float* __restrict__ a_in_p, const float* __restrict__ a_ep_p)
{
    constexpr int BM = 128, BN = 128, BK = 8;
    __shared__ __align__(16) float As[2][BK][2 * BM + 8];
    __shared__ __align__(16) float Bs[2][BK][BN];

    const int tid = threadIdx.x;
    const int bm = blockIdx.y * BM;
    const int bn = blockIdx.x * BN;

    float a_in = 0.f, a_ep = 0.f;
    if constexpr (IN_MODE >= 1) a_in = *a_in_p;
    if constexpr (EPI_PRELU || RES_MODE == 2) a_ep = *a_ep_p;

    const int ar  = tid >> 1;
    const int ak  = (tid & 1) << 2;
    const int bk  = tid >> 5;
    const int bn0 = (tid & 31) << 2;

    const bool kvec = (K & 3) == 0;
    const bool nvec = (N & 3) == 0;

    float4 aR, bR;

    auto loadAB = [&](int kt) {
        {
            int row = bm + ar;
            int k = kt + ak;
            float4 v  = make_float4(0.f, 0.f, 0.f, 0.f);
            float4 hv = make_float4(0.f, 0.f, 0.f, 0.f);
            if (row < M && k < K) {
                const float* p = A + (size_t)row * K + k;
                if (kvec) {
                    v = *reinterpret_cast<const float4*>(p);
                } else {
                    v.x = p[0];
                    if (k + 1 < K) v.y = p[1];
                    if (k + 2 < K) v.z = p[2];
                    if (k + 3 < K) v.w = p[3];
                }
                if constexpr (IN_MODE == 2) {
                    const float* q = Hh + (size_t)row * K + k;
                    if (kvec) {
                        hv = *reinterpret_cast<const float4*>(q);
                    } else {
                        hv.x = q[0];
                        if (k + 1 < K) hv.y = q[1];
                        if (k + 2 < K) hv.z = q[2];
                        if (k + 3 < K) hv.w = q[3];
                    }
                }
            }
            if constexpr (IN_MODE == 1) {
                v.x = preluf(v.x, a_in); v.y = preluf(v.y, a_in);
                v.z = preluf(v.z, a_in); v.w = preluf(v.w, a_in);
            } else if constexpr (IN_MODE == 2) {
                v.x = 0.5f * (preluf(v.x, a_in) + hv.x);
                v.y = 0.5f * (preluf(v.y, a_in) + hv.y);
                v.z = 0.5f * (preluf(v.z, a_in) + hv.z);
                v.w = 0.5f * (preluf(v.w, a_in) + hv.w);
            }
            aR = v;
        }
        {
            int k = kt + bk;
            int n = bn + bn0;
            float4 v = make_float4(0.f, 0.f, 0.f, 0.f);
            if (k < K && n < N) {
                const float* p = W + (size_t)k * N + n;
                if (nvec) {
                    v = *reinterpret_cast<const float4*>(p);
                } else {
                    v.x = p[0];
                    if (n + 1 < N) v.y = p[1];
                    if (n + 2 < N) v.z = p[2];
                    if (n + 3 < N) v.w = p[3];
                }
            }
            bR = v;
        }
    };

    auto stage = [&](int buf) {
        reinterpret_cast<unsigned long long*>(As[buf][ak + 0])[ar] = dupf(aR.x);
        reinterpret_cast<unsigned long long*>(As[buf][ak + 1])[ar] = dupf(aR.y);
        reinterpret_cast<unsigned long long*>(As[buf][ak + 2])[ar] = dupf(aR.z);
        reinterpret_cast<unsigned long long*>(As[buf][ak + 3])[ar] = dupf(aR.w);
        *reinterpret_cast<float4*>(&Bs[buf][bk][bn0]) = bR;
    };

    const int ty = tid >> 4;
    const int tx = tid & 15;

    unsigned long long acc[8][4];
#pragma unroll
    for (int i = 0; i < 8; ++i)
#pragma unroll
        for (int j = 0; j < 4; ++j) acc[i][j] = 0ull;

    const int tiles = (K + BK - 1) / BK;
    loadAB(0);
    stage(0);
    __syncthreads();

    int buf = 0;
    for (int t = 0; t < tiles; ++t) {
        const bool more = (t + 1 < tiles);
        if (more) loadAB((t + 1) * BK);
#pragma unroll
        for (int k = 0; k < BK; ++k) {
            const ulonglong2* ap =
                reinterpret_cast<const ulonglong2*>(&As[buf][k][ty << 4]);
            ulonglong2 a01 = ap[0], a23 = ap[1], a45 = ap[2], a67 = ap[3];
            ulonglong2 b01 = *reinterpret_cast<const ulonglong2*>(&Bs[buf][k][tx << 2]);
            ulonglong2 b23 = *reinterpret_cast<const ulonglong2*>(&Bs[buf][k][(tx << 2) + 64]);
            unsigned long long av[8] = {a01.x, a01.y, a23.x, a23.y,
                                        a45.x, a45.y, a67.x, a67.y};
#pragma unroll
            for (int i = 0; i < 8; ++i) {
                ffma2(acc[i][0], av[i], b01.x);
                ffma2(acc[i][1], av[i], b01.y);
                ffma2(acc[i][2], av[i], b23.x);
                ffma2(acc[i][3], av[i], b23.y);
            }
        }
        if (more) {
            stage(buf ^ 1);
            __syncthreads();
            buf ^= 1;
        }
    }

#pragma unroll
    for (int i = 0; i < 8; ++i) {
        const int m = bm + (ty << 3) + i;
        if (m >= M) continue;
#pragma unroll
        for (int g = 0; g < 2; ++g) {
            const int n0 = bn + (g << 6) + (tx << 2);
            float f0 = ull_lo(acc[i][2 * g]);
            float f1 = ull_hi(acc[i][2 * g]);
            float f2 = ull_lo(acc[i][2 * g + 1]);
            float f3 = ull_hi(acc[i][2 * g + 1]);
            if (nvec && n0 + 3 < N) {
                if constexpr (HAS_BIAS) {
                    float4 bv = *reinterpret_cast<const float4*>(bias + n0);
                    f0 += bv.x; f1 += bv.y; f2 += bv.z; f3 += bv.w;
                }
                if constexpr (RES_MODE == 1) {
                    float4 rv = *reinterpret_cast<const float4*>(R + (size_t)m * N + n0);
                    f0 += rv.x; f1 += rv.y; f2 += rv.z; f3 += rv.w;
                } else if constexpr (RES_MODE == 2) {
                    float4 rv = *reinterpret_cast<const float4*>(R + (size_t)m * N + n0);
                    f0 += preluf(rv.x, a_ep); f1 += preluf(rv.y, a_ep);
                    f2 += preluf(rv.z, a_ep); f3 += preluf(rv.w, a_ep);
                }
                if constexpr (EPI_PRELU) {
                    f0 = preluf(f0, a_ep); f1 = preluf(f1, a_ep);
                    f2 = preluf(f2, a_ep); f3 = preluf(f3, a_ep);
                }
                *reinterpret_cast<float4*>(C + (size_t)m * N + n0) =
                    make_float4(f0, f1, f2, f3);
            } else {
                float f[4] = {f0, f1, f2, f3};
#pragma unroll
                for (int j = 0; j < 4; ++j) {
                    const int n = n0 + j;
                    if (n < N) {
                        float v = f[j];
                        if constexpr (HAS_BIAS) v += bias[n];
                        if constexpr (RES_MODE == 1) v += R[(size_t)m * N + n];
                        if constexpr (RES_MODE == 2) v += preluf(R[(size_t)m * N + n], a_ep);
                        if constexpr (EPI_PRELU) v = preluf(v, a_ep);
                        C[(size_t)m * N + n] = v;
                    }
                }
            }
        }
    }
}

// ---------------- launch ----------------
extern "C" void kernel_launch(void* const* d_in, const int* in_sizes, int n_in,
                              void* d_out, int out_size)
{
    (void)in_sizes; (void)n_in; (void)out_size;

    const float* features  = (const float*)d_in[0];
    const float* label_emb = (const float*)d_in[1];
    const float* wa        = (const float*)d_in[2];
    const float* ba        = (const float*)d_in[3];
    const float* w0        = (const float*)d_in[4];
    const float* b0        = (const float*)d_in[5];
    const float* wg1       = (const float*)d_in[6];
    const float* wg2       = (const float*)d_in[7];
    const float* w_last    = (const float*)d_in[8];
    const float* b_last    = (const float*)d_in[9];
    const float* a_out     = (const float*)d_in[10];
    const float* wl0       = (const float*)d_in[11];
    const float* bl0       = (const float*)d_in[12];
    const float* wl1       = (const float*)d_in[13];
    const float* bl1       = (const float*)d_in[14];
    const float* wl2       = (const float*)d_in[15];
    const float* bl2       = (const float*)d_in[16];
    const float* wl3       = (const float*)d_in[17];
    const float* bl3       = (const float*)d_in[18];
    const float* a_lab     = (const float*)d_in[19];

    float *right, *x1, *x2, *x3, *xout;
    cudaGetSymbolAddress((void**)&right, g_right);
    cudaGetSymbolAddress((void**)&x1, g_x1);
    cudaGetSymbolAddress((void**)&x2, g_x2);
    cudaGetSymbolAddress((void**)&x3, g_x3);
    cudaGetSymbolAddress((void**)&xout, g_xout);

    __nv_bfloat16 *w0h, *w0l, *g1h, *g1l, *g2h, *g2l, *l1h, *l1l, *l2h, *l2l;
    cudaGetSymbolAddress((void**)&w0h, g_w0t_hi);
    cudaGetSymbolAddress((void**)&w0l, g_w0t_lo);
    cudaGetSymbolAddress((void**)&g1h, g_wg1t_hi);
    cudaGetSymbolAddress((void**)&g1l, g_wg1t_lo);
    cudaGetSymbolAddress((void**)&g2h, g_wg2t_hi);
    cudaGetSymbolAddress((void**)&g2l, g_wg2t_lo);
    cudaGetSymbolAddress((void**)&l1h, g_wl1t_hi);
    cudaGetSymbolAddress((void**)&l1l, g_wl1t_lo);
    cudaGetSymbolAddress((void**)&l2h, g_wl2t_hi);
    cudaGetSymbolAddress((void**)&l2l, g_wl2t_lo);

    cudaFuncSetAttribute(hmma_k<0, 1, 0, 0>, cudaFuncAttributeMaxDynamicSharedMemorySize, HM_SMEM);
    cudaFuncSetAttribute(hmma_k<2, 0, 0, 2>, cudaFuncAttributeMaxDynamicSharedMemorySize, HM_SMEM);
    cudaFuncSetAttribute(hmma_k<0, 1, 1, 0>, cudaFuncAttributeMaxDynamicSharedMemorySize, HM_SMEM);

    // 0) weight prep (transpose + bf16 split)
    split_wt_kernel<<<(256 * 512 + 255) / 256, 256>>>(w0,  w0h, w0l, F_DIM,  HID_DIM);
    split_wt_kernel<<<(512 * 512 + 255) / 256, 256>>>(wg1, g1h, g1l, HID_DIM, HID_DIM);
    split_wt_kernel<<<(512 * 512 + 255) / 256, 256>>>(wg2, g2h, g2l, HID_DIM, HID_DIM);
    split_wt_kernel<<<(512 * 512 + 255) / 256, 256>>>(wl1, l1h, l1l, HID_DIM, HID_DIM);
    split_wt_kernel<<<(512 * 512 + 255) / 256, 256>>>(wl2, l2h, l2l, HID_DIM, HID_DIM);

    // 1) fused attention -> right [N, F]
    attn_kernel<<<(N_DIM + 3) / 4, 128>>>(features, wa, ba, right);

    const dim3 hgrid(HID_DIM / 64, (N_DIM + 127) / 128);
    const dim3 hblk(256);
    auto sgrid = [](int M, int N) { return dim3((unsigned)((N + 127) / 128), (unsigned)((M + 127) / 128)); };
    dim3 sblk(256);

    // 2) x1 = right @ w0 + b0                    (HMMA, K=256)
    hmma_k<0, 1, 0, 0><<<hgrid, hblk, HM_SMEM>>>(
        right, nullptr, w0h, w0l, b0, nullptr, x1, N_DIM, HID_DIM, F_DIM, nullptr, nullptr);

    // 3) x2 = support(x1, x1) @ wg1 + prelu(x1)  (HMMA)
    hmma_k<2, 0, 0, 2><<<hgrid, hblk, HM_SMEM>>>(
        x1, x1, g1h, g1l, nullptr, x1, x2, N_DIM, HID_DIM, HID_DIM, a_out, a_out);

    // 4) x3 = support(x2, x1) @ wg2 + prelu(x2)  (HMMA)
    hmma_k<2, 0, 0, 2><<<hgrid, hblk, HM_SMEM>>>(
        x2, x1, g2h, g2l, nullptr, x2, x3, N_DIM, HID_DIM, HID_DIM, a_out, a_out);

    // 5) xout = prelu(x3) @ w_last + b_last      (SIMT, N=47)
    gemm_k<1, 1, 0, 0><<<sgrid(N_DIM, C_DIM), sblk>>>(
        x3, nullptr, w_last, b_last, nullptr, xout, N_DIM, C_DIM, HID_DIM, a_out, nullptr);

    // 6) y0 = prelu(label_emb @ wl0 + bl0)       (SIMT, K=47) -> x1
    gemm_k<0, 1, 1, 0><<<sgrid(N_DIM, HID_DIM), sblk>>>(
        label_emb, nullptr, wl0, bl0, nullptr, x1, N_DIM, HID_DIM, C_DIM, nullptr, a_lab);

    // 7) y1 = prelu(y0 @ wl1 + bl1)              (HMMA) -> x2
    hmma_k<0, 1, 1, 0><<<hgrid, hblk, HM_SMEM>>>(
        x1, nullptr, l1h, l1l, bl1, nullptr, x2, N_DIM, HID_DIM, HID_DIM, nullptr, a_lab);

    // 8) y2 = prelu(y1 @ wl2 + bl2)              (HMMA) -> x3
    hmma_k<0, 1, 1, 0><<<hgrid, hblk, HM_SMEM>>>(
        x2, nullptr, l2h, l2l, bl2, nullptr, x3, N_DIM, HID_DIM, HID_DIM, nullptr, a_lab);

    // 9) out = y2 @ wl3 + bl3 + xout             (SIMT, N=47)
    gemm_k<0, 1, 0, 1><<<sgrid(N_DIM, C_DIM), sblk>>>(
        x3, nullptr, wl3, bl3, xout, (float*)d_out, N_DIM, C_DIM, HID_DIM, nullptr, nullptr);
}

// round 15
// speedup vs baseline: 2.7004x; 1.1147x over previous
#include <cuda_runtime.h>
#include <cuda_bf16.h>
#include <cstdint>

#define H_DIM 10
#define N_DIM 100000
#define F_DIM 256
#define HID_DIM 512
#define C_DIM 47

// ---------------- scratch (device globals: no allocation allowed) ----------------
__device__ float g_right[(size_t)N_DIM * F_DIM];
__device__ float g_x1[(size_t)N_DIM * HID_DIM];
__device__ float g_x2[(size_t)N_DIM * HID_DIM];
__device__ float g_x3[(size_t)N_DIM * HID_DIM];
__device__ float g_xout[(size_t)N_DIM * C_DIM];
__device__ float g_lab_pad[(size_t)N_DIM * 64];        // label_emb padded K=47 -> 64

// split/transposed weights (bf16 hi/lo, K-major rows of W^T; some padded)
__device__ __nv_bfloat16 g_w0t_hi[512 * 256];
__device__ __nv_bfloat16 g_w0t_lo[512 * 256];
__device__ __nv_bfloat16 g_wg1t_hi[512 * 512];
__device__ __nv_bfloat16 g_wg1t_lo[512 * 512];
__device__ __nv_bfloat16 g_wg2t_hi[512 * 512];
__device__ __nv_bfloat16 g_wg2t_lo[512 * 512];
__device__ __nv_bfloat16 g_wl1t_hi[512 * 512];
__device__ __nv_bfloat16 g_wl1t_lo[512 * 512];
__device__ __nv_bfloat16 g_wl2t_hi[512 * 512];
__device__ __nv_bfloat16 g_wl2t_lo[512 * 512];
__device__ __nv_bfloat16 g_wlast_hi[64 * 512];          // w_last^T  (N 47->64 pad)
__device__ __nv_bfloat16 g_wlast_lo[64 * 512];
__device__ __nv_bfloat16 g_wl3t_hi[64 * 512];           // wl3^T     (N 47->64 pad)
__device__ __nv_bfloat16 g_wl3t_lo[64 * 512];
__device__ __nv_bfloat16 g_wl0t_hi[512 * 64];           // wl0^T     (K 47->64 pad)
__device__ __nv_bfloat16 g_wl0t_lo[512 * 64];

// ---------------- helpers ----------------
__device__ __forceinline__ float lrelu02(float x) { return x >= 0.f ? x : 0.2f * x; }
__device__ __forceinline__ float preluf(float x, float a) { return x >= 0.f ? x : a * x; }
__device__ __forceinline__ uint32_t pack_bf2(__nv_bfloat16 lo16, __nv_bfloat16 hi16) {
    return ((uint32_t)__bfloat16_as_ushort(hi16) << 16) | __bfloat16_as_ushort(lo16);
}

// mma.sync bf16 m16n8k16 (baseline PTX: compiles for compute_103, runs on tensor cores)
__device__ __forceinline__ void mma16816(float* c, const uint32_t* a, const uint32_t* b) {
    asm volatile("mma.sync.aligned.m16n8k16.row.col.f32.bf16.bf16.f32 "
                 "{%0,%1,%2,%3}, {%4,%5,%6,%7}, {%8,%9}, {%0,%1,%2,%3};"
                 : "+f"(c[0]), "+f"(c[1]), "+f"(c[2]), "+f"(c[3])
                 : "r"(a[0]), "r"(a[1]), "r"(a[2]), "r"(a[3]), "r"(b[0]), "r"(b[1]));
}

// ---------------- fused attention: one pass over features ----------------
__global__ __launch_bounds__(128)
void attn_kernel(const float* __restrict__ feat, const float* __restrict__ wa,
                 const float* __restrict__ ba_p, float* __restrict__ right)
{
    const int warp = threadIdx.x >> 5;
    const int lane = threadIdx.x & 31;
    const int n = blockIdx.x * 4 + warp;
    if (n >= N_DIM) return;

    const float4* wa4 = reinterpret_cast<const float4*>(wa);
    const float4 wl_a = wa4[lane];
    const float4 wl_b = wa4[32 + lane];
    const float4 wr_a = wa4[64 + lane];
    const float4 wr_b = wa4[96 + lane];
    const float ba = *ba_p;

    float4 fa[H_DIM], fb[H_DIM];
    float xl[H_DIM], xr[H_DIM];

#pragma unroll
    for (int h = 0; h < H_DIM; ++h) {
        const float4* f4 = reinterpret_cast<const float4*>(
            feat + ((size_t)h * N_DIM + (size_t)n) * F_DIM);
        fa[h] = f4[lane];
        fb[h] = f4[32 + lane];
        float dl = fa[h].x * wl_a.x + fa[h].y * wl_a.y + fa[h].z * wl_a.z + fa[h].w * wl_a.w
                 + fb[h].x * wl_b.x + fb[h].y * wl_b.y + fb[h].z * wl_b.z + fb[h].w * wl_b.w;
        float dr = fa[h].x * wr_a.x + fa[h].y * wr_a.y + fa[h].z * wr_a.z + fa[h].w * wr_a.w
                 + fb[h].x * wr_b.x + fb[h].y * wr_b.y + fb[h].z * wr_b.z + fb[h].w * wr_b.w;
#pragma unroll
        for (int off = 16; off; off >>= 1) {
            dl += __shfl_xor_sync(0xffffffffu, dl, off);
            dr += __shfl_xor_sync(0xffffffffu, dr, off);
        }
        xl[h] = dl;
        xr[h] = dr;
    }

    float sc[H_DIM];
    sc[0] = lrelu02(xl[0] + xr[0] + ba);
#pragma unroll
    for (int i = 1; i < H_DIM; ++i) {
        float mx = sc[0];
#pragma unroll
        for (int j = 1; j < i; ++j) mx = fmaxf(mx, sc[j]);
        float s = 0.f, accv = 0.f;
#pragma unroll
        for (int j = 0; j < i; ++j) {
            float e = __expf(sc[j] - mx);
            s += e;
            accv += e * xl[j];
        }
        sc[i] = lrelu02(accv / s + xr[i] + ba);
    }

    float mx = sc[0];
#pragma unroll
    for (int j = 1; j < H_DIM; ++j) mx = fmaxf(mx, sc[j]);
    float s = 0.f;
    float4 ra = make_float4(0.f, 0.f, 0.f, 0.f);
    float4 rb = make_float4(0.f, 0.f, 0.f, 0.f);
#pragma unroll
    for (int h = 0; h < H_DIM; ++h) {
        float e = __expf(sc[h] - mx);
        s += e;
        ra.x += e * fa[h].x; ra.y += e * fa[h].y; ra.z += e * fa[h].z; ra.w += e * fa[h].w;
        rb.x += e * fb[h].x; rb.y += e * fb[h].y; rb.z += e * fb[h].z; rb.w += e * fb[h].w;
    }
    float inv = 1.f / s;
    ra.x *= inv; ra.y *= inv; ra.z *= inv; ra.w *= inv;
    rb.x *= inv; rb.y *= inv; rb.z *= inv; rb.w *= inv;

    float4* out4 = reinterpret_cast<float4*>(right + (size_t)n * F_DIM);
    out4[lane] = ra;
    out4[32 + lane] = rb;
}

// ---------------- weight transpose + bf16 split (with optional padding) ---------
// in:  w [K, N] row-major.  out: hi/lo [Npad rows, Kpad] K-major, zero padded.
__global__ void split_wt_kernel(const float* __restrict__ w,
                                __nv_bfloat16* __restrict__ hi,
                                __nv_bfloat16* __restrict__ lo,
                                int K, int N, int Kpad, int Npad)
{
    int idx = blockIdx.x * 256 + threadIdx.x;
    if (idx >= Kpad * Npad) return;
    int n = idx / Kpad;
    int k = idx - n * Kpad;
    float v = (k < K && n < N) ? w[(size_t)k * N + n] : 0.f;
    __nv_bfloat16 h = __float2bfloat16(v);
    float rem = v - __bfloat162float(h);
    hi[idx] = h;
    lo[idx] = __float2bfloat16(rem);
}

// pad label_emb [N, 47] -> [N, 64] (zeros in tail)
__global__ void pad_label_kernel(const float* __restrict__ emb, float* __restrict__ out)
{
    size_t idx = (size_t)blockIdx.x * 256 + threadIdx.x;
    if (idx >= (size_t)N_DIM * 64) return;
    size_t n = idx >> 6;
    int k = (int)(idx & 63);
    out[idx] = (k < C_DIM) ? emb[n * C_DIM + k] : 0.f;
}

// ---------------- HMMA split-bf16 GEMM (mma.sync m16n8k16) ----------------
// CTA 256 thr / 8 warps, tile 128m x 64n, BK=32. Warp tile 32m x 32n.
// W pre-transposed/split (Whi/Wlo [Npad>=64-mult, K] K-major, zero padded).
// K % 32 == 0 (pad upstream). N may be ragged (guarded epilogue).
// IN_MODE: 0=A, 1=prelu(A), 2=0.5*(prelu(A)+H0).  RES_MODE: 0, 1=+R, 2=+prelu(R).
static constexpr int HM_LDA = 40;                       // bf16 per smem row (32 + pad)
static constexpr int HM_ASZ = 128 * HM_LDA * 2;
static constexpr int HM_BSZ = 64 * HM_LDA * 2;
static constexpr int HM_AHI = 0;
static constexpr int HM_ALO = HM_ASZ;
static constexpr int HM_BHI = 2 * HM_ASZ;
static constexpr int HM_BLO = 2 * HM_ASZ + HM_BSZ;
static constexpr int HM_BUF = 2 * HM_ASZ + 2 * HM_BSZ;  // 30720 B
static constexpr int HM_SMEM = 2 * HM_BUF;              // 61440 B

template<int IN_MODE, int HAS_BIAS, int EPI_PRELU, int RES_MODE>
__global__ __launch_bounds__(256)
void hmma_k(const float* __restrict__ A, const float* __restrict__ Hh,
            const __nv_bfloat16* __restrict__ Whi, const __nv_bfloat16* __restrict__ Wlo,
            const float* __restrict__ bias, const float* __restrict__ R,
            float* __restrict__ C, int M, int N, int K,
            const float* __restrict__ a_in_p, const float* __restrict__ a_ep_p)
{
    extern __shared__ char sm[];
    const int tid = threadIdx.x;
    const int lane = tid & 31;
    const int g  = lane >> 2;
    const int tg = lane & 3;
    const int w  = tid >> 5;
    const int mw = w & 3;
    const int nw = w >> 2;
    const int bm = blockIdx.y * 128;
    const int bn = blockIdx.x * 64;

    float a_in = 0.f, a_ep = 0.f;
    if constexpr (IN_MODE >= 1) a_in = *a_in_p;
    if constexpr (EPI_PRELU || RES_MODE == 2) a_ep = *a_ep_p;

    const int ar  = tid >> 1;
    const int akh = (tid & 1) * 16;
    const int brn = tid >> 2;
    const int bkc = (tid & 3) * 8;
    const int arow_g = bm + ar;
    const bool avalid = arow_g < M;

    float aregs[16];
    uint4 bhr, blr;

    auto load_regs = [&](int c) {
        if (avalid) {
            const float4* ap = reinterpret_cast<const float4*>(A + (size_t)arow_g * K + c * 32 + akh);
#pragma unroll
            for (int i = 0; i < 4; ++i) {
                float4 v = ap[i];
                if constexpr (IN_MODE == 2) {
                    const float4* hp = reinterpret_cast<const float4*>(Hh + (size_t)arow_g * K + c * 32 + akh);
                    float4 h = hp[i];
                    v.x = 0.5f * (preluf(v.x, a_in) + h.x);
                    v.y = 0.5f * (preluf(v.y, a_in) + h.y);
                    v.z = 0.5f * (preluf(v.z, a_in) + h.z);
                    v.w = 0.5f * (preluf(v.w, a_in) + h.w);
                } else if constexpr (IN_MODE == 1) {
                    v.x = preluf(v.x, a_in); v.y = preluf(v.y, a_in);
                    v.z = preluf(v.z, a_in); v.w = preluf(v.w, a_in);
                }
                aregs[4 * i + 0] = v.x; aregs[4 * i + 1] = v.y;
                aregs[4 * i + 2] = v.z; aregs[4 * i + 3] = v.w;
            }
        } else {
#pragma unroll
            for (int i = 0; i < 16; ++i) aregs[i] = 0.f;
        }
        bhr = *reinterpret_cast<const uint4*>(Whi + (size_t)(bn + brn) * K + c * 32 + bkc);
        blr = *reinterpret_cast<const uint4*>(Wlo + (size_t)(bn + brn) * K + c * 32 + bkc);
    };

    auto store_stage = [&](int buf) {
        char* base = sm + buf * HM_BUF;
        uint32_t hw[8], lw[8];
#pragma unroll
        for (int q = 0; q < 8; ++q) {
            __nv_bfloat16 h0 = __float2bfloat16(aregs[2 * q]);
            __nv_bfloat16 h1 = __float2bfloat16(aregs[2 * q + 1]);
            float r0 = aregs[2 * q] - __bfloat162float(h0);
            float r1 = aregs[2 * q + 1] - __bfloat162float(h1);
            hw[q] = pack_bf2(h0, h1);
            lw[q] = pack_bf2(__float2bfloat16(r0), __float2bfloat16(r1));
        }
        const int aoff = ar * (HM_LDA * 2) + akh * 2;
        *reinterpret_cast<uint4*>(base + HM_AHI + aoff)      = make_uint4(hw[0], hw[1], hw[2], hw[3]);
        *reinterpret_cast<uint4*>(base + HM_AHI + aoff + 16) = make_uint4(hw[4], hw[5], hw[6], hw[7]);
        *reinterpret_cast<uint4*>(base + HM_ALO + aoff)      = make_uint4(lw[0], lw[1], lw[2], lw[3]);
        *reinterpret_cast<uint4*>(base + HM_ALO + aoff + 16) = make_uint4(lw[4], lw[5], lw[6], lw[7]);
        const int boff = brn * (HM_LDA * 2) + bkc * 2;
        *reinterpret_cast<uint4*>(base + HM_BHI + boff) = bhr;
        *reinterpret_cast<uint4*>(base + HM_BLO + boff) = blr;
    };

    float c[2][4][4];
#pragma unroll
    for (int m = 0; m < 2; ++m)
#pragma unroll
        for (int j = 0; j < 4; ++j)
#pragma unroll
            for (int q = 0; q < 4; ++q) c[m][j][q] = 0.f;

    const int chunks = K / 32;
    load_regs(0);
    store_stage(0);
    __syncthreads();

    int buf = 0;
    for (int t = 0; t < chunks; ++t) {
        const bool more = (t + 1 < chunks);
        if (more) load_regs(t + 1);

        const char* base = sm + buf * HM_BUF;
        const char* pAhi = base + HM_AHI;
        const char* pAlo = base + HM_ALO;
        const char* pBhi = base + HM_BHI;
        const char* pBlo = base + HM_BLO;

#pragma unroll
        for (int ko = 0; ko < 32; ko += 16) {
            uint32_t bh[4][2], bl[4][2];
#pragma unroll
            for (int j = 0; j < 4; ++j) {
                const int nr = nw * 32 + j * 8 + g;
                const int o0 = nr * (HM_LDA * 2) + (ko + 2 * tg) * 2;
                const int o1 = nr * (HM_LDA * 2) + (ko + 8 + 2 * tg) * 2;
                bh[j][0] = *reinterpret_cast<const uint32_t*>(pBhi + o0);
                bh[j][1] = *reinterpret_cast<const uint32_t*>(pBhi + o1);
                bl[j][0] = *reinterpret_cast<const uint32_t*>(pBlo + o0);
                bl[j][1] = *reinterpret_cast<const uint32_t*>(pBlo + o1);
            }
#pragma unroll
            for (int m = 0; m < 2; ++m) {
                const int r0 = mw * 32 + m * 16 + g;
                const int r1 = r0 + 8;
                const int c0 = (ko + 2 * tg) * 2;
                const int c1 = (ko + 8 + 2 * tg) * 2;
                uint32_t ah[4], al[4];
                ah[0] = *reinterpret_cast<const uint32_t*>(pAhi + r0 * (HM_LDA * 2) + c0);
                ah[1] = *reinterpret_cast<const uint32_t*>(pAhi + r1 * (HM_LDA * 2) + c0);
                ah[2] = *reinterpret_cast<const uint32_t*>(pAhi + r0 * (HM_LDA * 2) + c1);
                ah[3] = *reinterpret_cast<const uint32_t*>(pAhi + r1 * (HM_LDA * 2) + c1);
                al[0] = *reinterpret_cast<const uint32_t*>(pAlo + r0 * (HM_LDA * 2) + c0);
                al[1] = *reinterpret_cast<const uint32_t*>(pAlo + r1 * (HM_LDA * 2) + c0);
                al[2] = *reinterpret_cast<const uint32_t*>(pAlo + r0 * (HM_LDA * 2) + c1);
                al[3] = *reinterpret_cast<const uint32_t*>(pAlo + r1 * (HM_LDA * 2) + c1);
#pragma unroll
                for (int j = 0; j < 4; ++j) {
                    mma16816(c[m][j], ah, bh[j]);
                    mma16816(c[m][j], ah, bl[j]);
                    mma16816(c[m][j], al, bh[j]);
                }
            }
        }

        if (more) {
            store_stage(buf ^ 1);
            __syncthreads();
            buf ^= 1;
        }
    }

    // ---- epilogue (guarded scalar path when N % 64 != 0) ----
    const bool nfull = ((N & 63) == 0);
#pragma unroll
    for (int m = 0; m < 2; ++m) {
        const int r0g = bm + mw * 32 + m * 16 + g;
        const int r1g = r0g + 8;
#pragma unroll
        for (int j = 0; j < 4; ++j) {
            const int col = bn + nw * 32 + j * 8 + 2 * tg;
            const bool c0ok = nfull || (col < N);
            const bool c1ok = nfull || (col + 1 < N);
            float bv0 = 0.f, bv1 = 0.f;
            if constexpr (HAS_BIAS) {
                if (c0ok) bv0 = bias[col];
                if (c1ok) bv1 = bias[col + 1];
            }
            const int rows[2] = {r0g, r1g};
            float fv[2][2] = {{c[m][j][0], c[m][j][1]}, {c[m][j][2], c[m][j][3]}};
#pragma unroll
            for (int rr = 0; rr < 2; ++rr) {
                const int r = rows[rr];
                if (r >= M) continue;
                float g0 = fv[rr][0] + bv0;
                float g1 = fv[rr][1] + bv1;
                if constexpr (RES_MODE == 1) {
                    if (c0ok) g0 += R[(size_t)r * N + col];
                    if (c1ok) g1 += R[(size_t)r * N + col + 1];
                } else if constexpr (RES_MODE == 2) {
                    if (c0ok) g0 += preluf(R[(size_t)r * N + col], a_ep);
                    if (c1ok) g1 += preluf(R[(size_t)r * N + col + 1], a_ep);
                }
                if constexpr (EPI_PRELU) { g0 = preluf(g0, a_ep); g1 = preluf(g1, a_ep); }
                if (nfull) {
                    *reinterpret_cast<float2*>(C + (size_t)r * N + col) = make_float2(g0, g1);
                } else {
                    if (c0ok) C[(size_t)r * N + col] = g0;
                    if (c1ok) C[(size_t)r * N + col + 1] = g1;
                }
            }
        }
    }
}

// ---------------- launch ----------------
extern "C" void kernel_launch(void* const* d_in, const int* in_sizes, int n_in,
                              void* d_out, int out_size)
{
    (void)in_sizes; (void)n_in; (void)out_size;

    const float* features  = (const float*)d_in[0];
    const float* label_emb = (const float*)d_in[1];
    const float* wa        = (const float*)d_in[2];
    const float* ba        = (const float*)d_in[3];
    const float* w0        = (const float*)d_in[4];
    const float* b0        = (const float*)d_in[5];
    const float* wg1       = (const float*)d_in[6];
    const float* wg2       = (const float*)d_in[7];
    const float* w_last    = (const float*)d_in[8];
    const float* b_last    = (const float*)d_in[9];
    const float* a_out     = (const float*)d_in[10];
    const float* wl0       = (const float*)d_in[11];
    const float* bl0       = (const float*)d_in[12];
    const float* wl1       = (const float*)d_in[13];
    const float* bl1       = (const float*)d_in[14];
    const float* wl2       = (const float*)d_in[15];
    const float* bl2       = (const float*)d_in[16];
    const float* wl3       = (const float*)d_in[17];
    const float* bl3       = (const float*)d_in[18];
    const float* a_lab     = (const float*)d_in[19];

    float *right, *x1, *x2, *x3, *xout, *labp;
    cudaGetSymbolAddress((void**)&right, g_right);
    cudaGetSymbolAddress((void**)&x1, g_x1);
    cudaGetSymbolAddress((void**)&x2, g_x2);
    cudaGetSymbolAddress((void**)&x3, g_x3);
    cudaGetSymbolAddress((void**)&xout, g_xout);
    cudaGetSymbolAddress((void**)&labp, g_lab_pad);

    __nv_bfloat16 *w0h, *w0l, *g1h, *g1l, *g2h, *g2l, *l1h, *l1l, *l2h, *l2l;
    __nv_bfloat16 *wlh, *wll, *l3h, *l3l, *l0h, *l0l;
    cudaGetSymbolAddress((void**)&w0h, g_w0t_hi);
    cudaGetSymbolAddress((void**)&w0l, g_w0t_lo);
    cudaGetSymbolAddress((void**)&g1h, g_wg1t_hi);
    cudaGetSymbolAddress((void**)&g1l, g_wg1t_lo);
    cudaGetSymbolAddress((void**)&g2h, g_wg2t_hi);
    cudaGetSymbolAddress((void**)&g2l, g_wg2t_lo);
    cudaGetSymbolAddress((void**)&l1h, g_wl1t_hi);
    cudaGetSymbolAddress((void**)&l1l, g_wl1t_lo);
    cudaGetSymbolAddress((void**)&l2h, g_wl2t_hi);
    cudaGetSymbolAddress((void**)&l2l, g_wl2t_lo);
    cudaGetSymbolAddress((void**)&wlh, g_wlast_hi);
    cudaGetSymbolAddress((void**)&wll, g_wlast_lo);
    cudaGetSymbolAddress((void**)&l3h, g_wl3t_hi);
    cudaGetSymbolAddress((void**)&l3l, g_wl3t_lo);
    cudaGetSymbolAddress((void**)&l0h, g_wl0t_hi);
    cudaGetSymbolAddress((void**)&l0l, g_wl0t_lo);

    cudaFuncSetAttribute(hmma_k<0, 1, 0, 0>, cudaFuncAttributeMaxDynamicSharedMemorySize, HM_SMEM);
    cudaFuncSetAttribute(hmma_k<2, 0, 0, 2>, cudaFuncAttributeMaxDynamicSharedMemorySize, HM_SMEM);
    cudaFuncSetAttribute(hmma_k<0, 1, 1, 0>, cudaFuncAttributeMaxDynamicSharedMemorySize, HM_SMEM);
    cudaFuncSetAttribute(hmma_k<1, 1, 0, 0>, cudaFuncAttributeMaxDynamicSharedMemorySize, HM_SMEM);
    cudaFuncSetAttribute(hmma_k<0, 1, 0, 1>, cudaFuncAttributeMaxDynamicSharedMemorySize, HM_SMEM);

    // 0) weight prep (transpose + bf16 split, padded where needed)
    auto sgrid1 = [](int total) { return (total + 255) / 256; };
    split_wt_kernel<<<sgrid1(512 * 256), 256>>>(w0,     w0h, w0l, F_DIM,   HID_DIM, F_DIM,   HID_DIM);
    split_wt_kernel<<<sgrid1(512 * 512), 256>>>(wg1,    g1h, g1l, HID_DIM, HID_DIM, HID_DIM, HID_DIM);
    split_wt_kernel<<<sgrid1(512 * 512), 256>>>(wg2,    g2h, g2l, HID_DIM, HID_DIM, HID_DIM, HID_DIM);
    split_wt_kernel<<<sgrid1(512 * 512), 256>>>(wl1,    l1h, l1l, HID_DIM, HID_DIM, HID_DIM, HID_DIM);
    split_wt_kernel<<<sgrid1(512 * 512), 256>>>(wl2,    l2h, l2l, HID_DIM, HID_DIM, HID_DIM, HID_DIM);
    split_wt_kernel<<<sgrid1(64 * 512),  256>>>(w_last, wlh, wll, HID_DIM, C_DIM,   HID_DIM, 64);
    split_wt_kernel<<<sgrid1(64 * 512),  256>>>(wl3,    l3h, l3l, HID_DIM, C_DIM,   HID_DIM, 64);
    split_wt_kernel<<<sgrid1(512 * 64),  256>>>(wl0,    l0h, l0l, C_DIM,   HID_DIM, 64,      HID_DIM);
    pad_label_kernel<<<(int)(((size_t)N_DIM * 64 + 255) / 256), 256>>>(label_emb, labp);

    // 1) fused attention -> right [N, F]
    attn_kernel<<<(N_DIM + 3) / 4, 128>>>(features, wa, ba, right);

    auto hgrid = [](int N) { return dim3((unsigned)((N + 63) / 64), (unsigned)((N_DIM + 127) / 128)); };
    const dim3 hblk(256);

    // 2) x1 = right @ w0 + b0                    (K=256)
    hmma_k<0, 1, 0, 0><<<hgrid(HID_DIM), hblk, HM_SMEM>>>(
        right, nullptr, w0h, w0l, b0, nullptr, x1, N_DIM, HID_DIM, F_DIM, nullptr, nullptr);

    // 3) x2 = support(x1, x1) @ wg1 + prelu(x1)
    hmma_k<2, 0, 0, 2><<<hgrid(HID_DIM), hblk, HM_SMEM>>>(
        x1, x1, g1h, g1l, nullptr, x1, x2, N_DIM, HID_DIM, HID_DIM, a_out, a_out);

    // 4) x3 = support(x2, x1) @ wg2 + prelu(x2)
    hmma_k<2, 0, 0, 2><<<hgrid(HID_DIM), hblk, HM_SMEM>>>(
        x2, x1, g2h, g2l, nullptr, x2, x3, N_DIM, HID_DIM, HID_DIM, a_out, a_out);

    // 5) xout = prelu(x3) @ w_last + b_last      (N=47 ragged)
    hmma_k<1, 1, 0, 0><<<hgrid(C_DIM), hblk, HM_SMEM>>>(
        x3, nullptr, wlh, wll, b_last, nullptr, xout, N_DIM, C_DIM, HID_DIM, a_out, nullptr);

    // 6) y0 = prelu(lab_pad @ wl0 + bl0)         (K padded to 64) -> x1
    hmma_k<0, 1, 1, 0><<<hgrid(HID_DIM), hblk, HM_SMEM>>>(
        labp, nullptr, l0h, l0l, bl0, nullptr, x1, N_DIM, HID_DIM, 64, nullptr, a_lab);

    // 7) y1 = prelu(y0 @ wl1 + bl1) -> x2
    hmma_k<0, 1, 1, 0><<<hgrid(HID_DIM), hblk, HM_SMEM>>>(
        x1, nullptr, l1h, l1l, bl1, nullptr, x2, N_DIM, HID_DIM, HID_DIM, nullptr, a_lab);

    // 8) y2 = prelu(y1 @ wl2 + bl2) -> x3
    hmma_k<0, 1, 1, 0><<<hgrid(HID_DIM), hblk, HM_SMEM>>>(
        x2, nullptr, l2h, l2l, bl2, nullptr, x3, N_DIM, HID_DIM, HID_DIM, nullptr, a_lab);

    // 9) out = y2 @ wl3 + bl3 + xout             (N=47 ragged)
    hmma_k<0, 1, 0, 1><<<hgrid(C_DIM), hblk, HM_SMEM>>>(
        x3, nullptr, l3h, l3l, bl3, xout, (float*)d_out, N_DIM, C_DIM, HID_DIM, nullptr, nullptr);
}

// round 16
// speedup vs baseline: 3.1041x; 1.1495x over previous
#include <cuda_runtime.h>
#include <cuda_bf16.h>
#include <cstdint>

#define H_DIM 10
#define N_DIM 100000
#define F_DIM 256
#define HID_DIM 512
#define C_DIM 47

// ---------------- scratch (device globals: no allocation allowed) ----------------
__device__ float g_right[(size_t)N_DIM * F_DIM];
__device__ float g_x1[(size_t)N_DIM * HID_DIM];
__device__ float g_x2[(size_t)N_DIM * HID_DIM];
__device__ float g_x3[(size_t)N_DIM * HID_DIM];
__device__ float g_xout[(size_t)N_DIM * C_DIM];
__device__ float g_lab_pad[(size_t)N_DIM * 64];        // label_emb padded K=47 -> 64

// split/transposed weights (bf16 hi/lo, K-major rows of W^T; some padded)
__device__ __nv_bfloat16 g_w0t_hi[512 * 256];
__device__ __nv_bfloat16 g_w0t_lo[512 * 256];
__device__ __nv_bfloat16 g_wg1t_hi[512 * 512];
__device__ __nv_bfloat16 g_wg1t_lo[512 * 512];
__device__ __nv_bfloat16 g_wg2t_hi[512 * 512];
__device__ __nv_bfloat16 g_wg2t_lo[512 * 512];
__device__ __nv_bfloat16 g_wl1t_hi[512 * 512];
__device__ __nv_bfloat16 g_wl1t_lo[512 * 512];
__device__ __nv_bfloat16 g_wl2t_hi[512 * 512];
__device__ __nv_bfloat16 g_wl2t_lo[512 * 512];
__device__ __nv_bfloat16 g_wlast_hi[64 * 512];          // w_last^T  (N 47->64 pad)
__device__ __nv_bfloat16 g_wlast_lo[64 * 512];
__device__ __nv_bfloat16 g_wl3t_hi[64 * 512];           // wl3^T     (N 47->64 pad)
__device__ __nv_bfloat16 g_wl3t_lo[64 * 512];
__device__ __nv_bfloat16 g_wl0t_hi[512 * 64];           // wl0^T     (K 47->64 pad)
__device__ __nv_bfloat16 g_wl0t_lo[512 * 64];

// ---------------- helpers ----------------
__device__ __forceinline__ float lrelu02(float x) { return x >= 0.f ? x : 0.2f * x; }
__device__ __forceinline__ float preluf(float x, float a) { return x >= 0.f ? x : a * x; }

// mma.sync bf16 m16n8k16 (baseline PTX: compiles for compute_103, runs on tensor cores)
__device__ __forceinline__ void mma16816(float* c, const uint32_t* a, const uint32_t* b) {
    asm volatile("mma.sync.aligned.m16n8k16.row.col.f32.bf16.bf16.f32 "
                 "{%0,%1,%2,%3}, {%4,%5,%6,%7}, {%8,%9}, {%0,%1,%2,%3};"
                 : "+f"(c[0]), "+f"(c[1]), "+f"(c[2]), "+f"(c[3])
                 : "r"(a[0]), "r"(a[1]), "r"(a[2]), "r"(a[3]), "r"(b[0]), "r"(b[1]));
}
// ldmatrix x4 (baseline PTX sm_75+)
__device__ __forceinline__ void ldsm_x4(uint32_t* r, uint32_t saddr) {
    asm volatile("ldmatrix.sync.aligned.m8n8.x4.shared.b16 {%0,%1,%2,%3}, [%4];"
                 : "=r"(r[0]), "=r"(r[1]), "=r"(r[2]), "=r"(r[3]) : "r"(saddr));
}
// pack 2 floats -> bf16x2 (hi half = first src)
__device__ __forceinline__ uint32_t cvt_bf16x2(float hi, float lo) {
    uint32_t d;
    asm("cvt.rn.bf16x2.f32 %0, %1, %2;" : "=r"(d) : "f"(hi), "f"(lo));
    return d;
}

// ---------------- fused attention: one pass over features ----------------
__global__ __launch_bounds__(128)
void attn_kernel(const float* __restrict__ feat, const float* __restrict__ wa,
                 const float* __restrict__ ba_p, float* __restrict__ right)
{
    const int warp = threadIdx.x >> 5;
    const int lane = threadIdx.x & 31;
    const int n = blockIdx.x * 4 + warp;
    if (n >= N_DIM) return;

    const float4* wa4 = reinterpret_cast<const float4*>(wa);
    const float4 wl_a = wa4[lane];
    const float4 wl_b = wa4[32 + lane];
    const float4 wr_a = wa4[64 + lane];
    const float4 wr_b = wa4[96 + lane];
    const float ba = *ba_p;

    float4 fa[H_DIM], fb[H_DIM];
    float xl[H_DIM], xr[H_DIM];

#pragma unroll
    for (int h = 0; h < H_DIM; ++h) {
        const float4* f4 = reinterpret_cast<const float4*>(
            feat + ((size_t)h * N_DIM + (size_t)n) * F_DIM);
        fa[h] = f4[lane];
        fb[h] = f4[32 + lane];
        float dl = fa[h].x * wl_a.x + fa[h].y * wl_a.y + fa[h].z * wl_a.z + fa[h].w * wl_a.w
                 + fb[h].x * wl_b.x + fb[h].y * wl_b.y + fb[h].z * wl_b.z + fb[h].w * wl_b.w;
        float dr = fa[h].x * wr_a.x + fa[h].y * wr_a.y + fa[h].z * wr_a.z + fa[h].w * wr_a.w
                 + fb[h].x * wr_b.x + fb[h].y * wr_b.y + fb[h].z * wr_b.z + fb[h].w * wr_b.w;
#pragma unroll
        for (int off = 16; off; off >>= 1) {
            dl += __shfl_xor_sync(0xffffffffu, dl, off);
            dr += __shfl_xor_sync(0xffffffffu, dr, off);
        }
        xl[h] = dl;
        xr[h] = dr;
    }

    float sc[H_DIM];
    sc[0] = lrelu02(xl[0] + xr[0] + ba);
#pragma unroll
    for (int i = 1; i < H_DIM; ++i) {
        float mx = sc[0];
#pragma unroll
        for (int j = 1; j < i; ++j) mx = fmaxf(mx, sc[j]);
        float s = 0.f, accv = 0.f;
#pragma unroll
        for (int j = 0; j < i; ++j) {
            float e = __expf(sc[j] - mx);
            s += e;
            accv += e * xl[j];
        }
        sc[i] = lrelu02(accv / s + xr[i] + ba);
    }

    float mx = sc[0];
#pragma unroll
    for (int j = 1; j < H_DIM; ++j) mx = fmaxf(mx, sc[j]);
    float s = 0.f;
    float4 ra = make_float4(0.f, 0.f, 0.f, 0.f);
    float4 rb = make_float4(0.f, 0.f, 0.f, 0.f);
#pragma unroll
    for (int h = 0; h < H_DIM; ++h) {
        float e = __expf(sc[h] - mx);
        s += e;
        ra.x += e * fa[h].x; ra.y += e * fa[h].y; ra.z += e * fa[h].z; ra.w += e * fa[h].w;
        rb.x += e * fb[h].x; rb.y += e * fb[h].y; rb.z += e * fb[h].z; rb.w += e * fb[h].w;
    }
    float inv = 1.f / s;
    ra.x *= inv; ra.y *= inv; ra.z *= inv; ra.w *= inv;
    rb.x *= inv; rb.y *= inv; rb.z *= inv; rb.w *= inv;

    float4* out4 = reinterpret_cast<float4*>(right + (size_t)n * F_DIM);
    out4[lane] = ra;
    out4[32 + lane] = rb;
}

// ---------------- weight transpose + bf16 split (with optional padding) ---------
__global__ void split_wt_kernel(const float* __restrict__ w,
                                __nv_bfloat16* __restrict__ hi,
                                __nv_bfloat16* __restrict__ lo,
                                int K, int N, int Kpad, int Npad)
{
    int idx = blockIdx.x * 256 + threadIdx.x;
    if (idx >= Kpad * Npad) return;
    int n = idx / Kpad;
    int k = idx - n * Kpad;
    float v = (k < K && n < N) ? w[(size_t)k * N + n] : 0.f;
    __nv_bfloat16 h = __float2bfloat16(v);
    float rem = v - __bfloat162float(h);
    hi[idx] = h;
    lo[idx] = __float2bfloat16(rem);
}

// pad label_emb [N, 47] -> [N, 64] (zeros in tail)
__global__ void pad_label_kernel(const float* __restrict__ emb, float* __restrict__ out)
{
    size_t idx = (size_t)blockIdx.x * 256 + threadIdx.x;
    if (idx >= (size_t)N_DIM * 64) return;
    size_t n = idx >> 6;
    int k = (int)(idx & 63);
    out[idx] = (k < C_DIM) ? emb[n * C_DIM + k] : 0.f;
}

// ---------------- HMMA split-bf16 GEMM (mma.sync m16n8k16 + ldmatrix) ----------
// CTA 256 thr / 8 warps, tile 128m x 64n, BK=32. Warp tile 32m x 32n.
static constexpr int HM_LDA = 40;                       // bf16 per smem row (32 + pad)
static constexpr int HM_LDA2 = HM_LDA * 2;              // bytes per row (80)
static constexpr int HM_ASZ = 128 * HM_LDA2;
static constexpr int HM_BSZ = 64 * HM_LDA2;
static constexpr int HM_AHI = 0;
static constexpr int HM_ALO = HM_ASZ;
static constexpr int HM_BHI = 2 * HM_ASZ;
static constexpr int HM_BLO = 2 * HM_ASZ + HM_BSZ;
static constexpr int HM_BUF = 2 * HM_ASZ + 2 * HM_BSZ;  // 30720 B
static constexpr int HM_SMEM = 2 * HM_BUF;              // 61440 B

template<int IN_MODE, int HAS_BIAS, int EPI_PRELU, int RES_MODE>
__global__ __launch_bounds__(256)
void hmma_k(const float* __restrict__ A, const float* __restrict__ Hh,
            const __nv_bfloat16* __restrict__ Whi, const __nv_bfloat16* __restrict__ Wlo,
            const float* __restrict__ bias, const float* __restrict__ R,
            float* __restrict__ C, int M, int N, int K,
            const float* __restrict__ a_in_p, const float* __restrict__ a_ep_p)
{
    extern __shared__ char sm[];
    const uint32_t sbase = (uint32_t)__cvta_generic_to_shared(sm);
    const int tid = threadIdx.x;
    const int lane = tid & 31;
    const int g  = lane >> 2;
    const int tg = lane & 3;
    const int w  = tid >> 5;
    const int mw = w & 3;
    const int nw = w >> 2;
    const int bm = blockIdx.y * 128;
    const int bn = blockIdx.x * 64;

    float a_in = 0.f, a_ep = 0.f;
    if constexpr (IN_MODE >= 1) a_in = *a_in_p;
    if constexpr (EPI_PRELU || RES_MODE == 2) a_ep = *a_ep_p;

    // ldmatrix per-lane addressing
    const int q8 = lane >> 3, r8 = lane & 7;
    const int a_row_l = mw * 32 + ((q8 & 1) << 3) + r8;   // + m*16 per call
    const int a_col_l = (q8 >> 1) << 4;                   // bytes; + ko*2 per call
    const int b_row_l = nw * 32 + ((q8 >> 1) << 3) + r8;  // + jp*16 per call
    const int b_col_l = (q8 & 1) << 4;                    // bytes; + ko*2 per call

    // staging assignment
    const int ar  = tid >> 1;
    const int akh = (tid & 1) * 16;
    const int brn = tid >> 2;
    const int bkc = (tid & 3) * 8;
    const int arow_g = bm + ar;
    const bool avalid = arow_g < M;

    float aregs[16];
    uint4 bhr, blr;

    auto load_regs = [&](int c) {
        if (avalid) {
            const float4* ap = reinterpret_cast<const float4*>(A + (size_t)arow_g * K + c * 32 + akh);
#pragma unroll
            for (int i = 0; i < 4; ++i) {
                float4 v = ap[i];
                if constexpr (IN_MODE == 2) {
                    const float4* hp = reinterpret_cast<const float4*>(Hh + (size_t)arow_g * K + c * 32 + akh);
                    float4 h = hp[i];
                    v.x = 0.5f * (preluf(v.x, a_in) + h.x);
                    v.y = 0.5f * (preluf(v.y, a_in) + h.y);
                    v.z = 0.5f * (preluf(v.z, a_in) + h.z);
                    v.w = 0.5f * (preluf(v.w, a_in) + h.w);
                } else if constexpr (IN_MODE == 1) {
                    v.x = preluf(v.x, a_in); v.y = preluf(v.y, a_in);
                    v.z = preluf(v.z, a_in); v.w = preluf(v.w, a_in);
                }
                aregs[4 * i + 0] = v.x; aregs[4 * i + 1] = v.y;
                aregs[4 * i + 2] = v.z; aregs[4 * i + 3] = v.w;
            }
        } else {
#pragma unroll
            for (int i = 0; i < 16; ++i) aregs[i] = 0.f;
        }
        bhr = *reinterpret_cast<const uint4*>(Whi + (size_t)(bn + brn) * K + c * 32 + bkc);
        blr = *reinterpret_cast<const uint4*>(Wlo + (size_t)(bn + brn) * K + c * 32 + bkc);
    };

    auto store_stage = [&](int buf) {
        char* base = sm + buf * HM_BUF;
        uint32_t hw[8], lw[8];
#pragma unroll
        for (int q = 0; q < 8; ++q) {
            float f0 = aregs[2 * q], f1 = aregs[2 * q + 1];
            uint32_t h2 = cvt_bf16x2(f1, f0);
            float h0f = __uint_as_float(h2 << 16);
            float h1f = __uint_as_float(h2 & 0xffff0000u);
            hw[q] = h2;
            lw[q] = cvt_bf16x2(f1 - h1f, f0 - h0f);
        }
        const int aoff = ar * HM_LDA2 + akh * 2;
        *reinterpret_cast<uint4*>(base + HM_AHI + aoff)      = make_uint4(hw[0], hw[1], hw[2], hw[3]);
        *reinterpret_cast<uint4*>(base + HM_AHI + aoff + 16) = make_uint4(hw[4], hw[5], hw[6], hw[7]);
        *reinterpret_cast<uint4*>(base + HM_ALO + aoff)      = make_uint4(lw[0], lw[1], lw[2], lw[3]);
        *reinterpret_cast<uint4*>(base + HM_ALO + aoff + 16) = make_uint4(lw[4], lw[5], lw[6], lw[7]);
        const int boff = brn * HM_LDA2 + bkc * 2;
        *reinterpret_cast<uint4*>(base + HM_BHI + boff) = bhr;
        *reinterpret_cast<uint4*>(base + HM_BLO + boff) = blr;
    };

    float c[2][4][4];
#pragma unroll
    for (int m = 0; m < 2; ++m)
#pragma unroll
        for (int j = 0; j < 4; ++j)
#pragma unroll
            for (int q = 0; q < 4; ++q) c[m][j][q] = 0.f;

    const int chunks = K / 32;
    load_regs(0);
    store_stage(0);
    __syncthreads();

    int buf = 0;
    for (int t = 0; t < chunks; ++t) {
        const bool more = (t + 1 < chunks);
        if (more) load_regs(t + 1);

        const uint32_t sb = sbase + buf * HM_BUF;

#pragma unroll
        for (int ko = 0; ko < 32; ko += 16) {
            uint32_t bh[4][2], bl[4][2], tr[4];
#pragma unroll
            for (int jp = 0; jp < 2; ++jp) {
                const uint32_t boff = (uint32_t)((b_row_l + jp * 16) * HM_LDA2 + b_col_l + ko * 2);
                ldsm_x4(tr, sb + HM_BHI + boff);
                bh[2 * jp][0] = tr[0]; bh[2 * jp][1] = tr[1];
                bh[2 * jp + 1][0] = tr[2]; bh[2 * jp + 1][1] = tr[3];
                ldsm_x4(tr, sb + HM_BLO + boff);
                bl[2 * jp][0] = tr[0]; bl[2 * jp][1] = tr[1];
                bl[2 * jp + 1][0] = tr[2]; bl[2 * jp + 1][1] = tr[3];
            }
#pragma unroll
            for (int m = 0; m < 2; ++m) {
                const uint32_t aoff = (uint32_t)((a_row_l + m * 16) * HM_LDA2 + a_col_l + ko * 2);
                uint32_t ah[4], al[4];
                ldsm_x4(ah, sb + HM_AHI + aoff);
                ldsm_x4(al, sb + HM_ALO + aoff);
#pragma unroll
                for (int j = 0; j < 4; ++j) {
                    mma16816(c[m][j], ah, bh[j]);
                    mma16816(c[m][j], ah, bl[j]);
                    mma16816(c[m][j], al, bh[j]);
                }
            }
        }

        if (more) {
            store_stage(buf ^ 1);
            __syncthreads();
            buf ^= 1;
        }
    }

    // ---- epilogue (guarded scalar path when N % 64 != 0) ----
    const bool nfull = ((N & 63) == 0);
#pragma unroll
    for (int m = 0; m < 2; ++m) {
        const int r0g = bm + mw * 32 + m * 16 + g;
        const int r1g = r0g + 8;
#pragma unroll
        for (int j = 0; j < 4; ++j) {
            const int col = bn + nw * 32 + j * 8 + 2 * tg;
            const bool c0ok = nfull || (col < N);
            const bool c1ok = nfull || (col + 1 < N);
            float bv0 = 0.f, bv1 = 0.f;
            if constexpr (HAS_BIAS) {
                if (c0ok) bv0 = bias[col];
                if (c1ok) bv1 = bias[col + 1];
            }
            const int rows[2] = {r0g, r1g};
            float fv[2][2] = {{c[m][j][0], c[m][j][1]}, {c[m][j][2], c[m][j][3]}};
#pragma unroll
            for (int rr = 0; rr < 2; ++rr) {
                const int r = rows[rr];
                if (r >= M) continue;
                float g0 = fv[rr][0] + bv0;
                float g1 = fv[rr][1] + bv1;
                if constexpr (RES_MODE == 1) {
                    if (c0ok) g0 += R[(size_t)r * N + col];
                    if (c1ok) g1 += R[(size_t)r * N + col + 1];
                } else if constexpr (RES_MODE == 2) {
                    if (c0ok) g0 += preluf(R[(size_t)r * N + col], a_ep);
                    if (c1ok) g1 += preluf(R[(size_t)r * N + col + 1], a_ep);
                }
                if constexpr (EPI_PRELU) { g0 = preluf(g0, a_ep); g1 = preluf(g1, a_ep); }
                if (nfull) {
                    *reinterpret_cast<float2*>(C + (size_t)r * N + col) = make_float2(g0, g1);
                } else {
                    if (c0ok) C[(size_t)r * N + col] = g0;
                    if (c1ok) C[(size_t)r * N + col + 1] = g1;
                }
            }
        }
    }
}

// ---------------- launch ----------------
extern "C" void kernel_launch(void* const* d_in, const int* in_sizes, int n_in,
                              void* d_out, int out_size)
{
    (void)in_sizes; (void)n_in; (void)out_size;

    const float* features  = (const float*)d_in[0];
    const float* label_emb = (const float*)d_in[1];
    const float* wa        = (const float*)d_in[2];
    const float* ba        = (const float*)d_in[3];
    const float* w0        = (const float*)d_in[4];
    const float* b0        = (const float*)d_in[5];
    const float* wg1       = (const float*)d_in[6];
    const float* wg2       = (const float*)d_in[7];
    const float* w_last    = (const float*)d_in[8];
    const float* b_last    = (const float*)d_in[9];
    const float* a_out     = (const float*)d_in[10];
    const float* wl0       = (const float*)d_in[11];
    const float* bl0       = (const float*)d_in[12];
    const float* wl1       = (const float*)d_in[13];
    const float* bl1       = (const float*)d_in[14];
    const float* wl2       = (const float*)d_in[15];
    const float* bl2       = (const float*)d_in[16];
    const float* wl3       = (const float*)d_in[17];
    const float* bl3       = (const float*)d_in[18];
    const float* a_lab     = (const float*)d_in[19];

    float *right, *x1, *x2, *x3, *xout, *labp;
    cudaGetSymbolAddress((void**)&right, g_right);
    cudaGetSymbolAddress((void**)&x1, g_x1);
    cudaGetSymbolAddress((void**)&x2, g_x2);
    cudaGetSymbolAddress((void**)&x3, g_x3);
    cudaGetSymbolAddress((void**)&xout, g_xout);
    cudaGetSymbolAddress((void**)&labp, g_lab_pad);

    __nv_bfloat16 *w0h, *w0l, *g1h, *g1l, *g2h, *g2l, *l1h, *l1l, *l2h, *l2l;
    __nv_bfloat16 *wlh, *wll, *l3h, *l3l, *l0h, *l0l;
    cudaGetSymbolAddress((void**)&w0h, g_w0t_hi);
    cudaGetSymbolAddress((void**)&w0l, g_w0t_lo);
    cudaGetSymbolAddress((void**)&g1h, g_wg1t_hi);
    cudaGetSymbolAddress((void**)&g1l, g_wg1t_lo);
    cudaGetSymbolAddress((void**)&g2h, g_wg2t_hi);
    cudaGetSymbolAddress((void**)&g2l, g_wg2t_lo);
    cudaGetSymbolAddress((void**)&l1h, g_wl1t_hi);
    cudaGetSymbolAddress((void**)&l1l, g_wl1t_lo);
    cudaGetSymbolAddress((void**)&l2h, g_wl2t_hi);
    cudaGetSymbolAddress((void**)&l2l, g_wl2t_lo);
    cudaGetSymbolAddress((void**)&wlh, g_wlast_hi);
    cudaGetSymbolAddress((void**)&wll, g_wlast_lo);
    cudaGetSymbolAddress((void**)&l3h, g_wl3t_hi);
    cudaGetSymbolAddress((void**)&l3l, g_wl3t_lo);
    cudaGetSymbolAddress((void**)&l0h, g_wl0t_hi);
    cudaGetSymbolAddress((void**)&l0l, g_wl0t_lo);

    cudaFuncSetAttribute(hmma_k<0, 1, 0, 0>, cudaFuncAttributeMaxDynamicSharedMemorySize, HM_SMEM);
    cudaFuncSetAttribute(hmma_k<2, 0, 0, 2>, cudaFuncAttributeMaxDynamicSharedMemorySize, HM_SMEM);
    cudaFuncSetAttribute(hmma_k<0, 1, 1, 0>, cudaFuncAttributeMaxDynamicSharedMemorySize, HM_SMEM);
    cudaFuncSetAttribute(hmma_k<1, 1, 0, 0>, cudaFuncAttributeMaxDynamicSharedMemorySize, HM_SMEM);
    cudaFuncSetAttribute(hmma_k<0, 1, 0, 1>, cudaFuncAttributeMaxDynamicSharedMemorySize, HM_SMEM);

    // 0) weight prep (transpose + bf16 split, padded where needed)
    auto sgrid1 = [](int total) { return (total + 255) / 256; };
    split_wt_kernel<<<sgrid1(512 * 256), 256>>>(w0,     w0h, w0l, F_DIM,   HID_DIM, F_DIM,   HID_DIM);
    split_wt_kernel<<<sgrid1(512 * 512), 256>>>(wg1,    g1h, g1l, HID_DIM, HID_DIM, HID_DIM, HID_DIM);
    split_wt_kernel<<<sgrid1(512 * 512), 256>>>(wg2,    g2h, g2l, HID_DIM, HID_DIM, HID_DIM, HID_DIM);
    split_wt_kernel<<<sgrid1(512 * 512), 256>>>(wl1,    l1h, l1l, HID_DIM, HID_DIM, HID_DIM, HID_DIM);
    split_wt_kernel<<<sgrid1(512 * 512), 256>>>(wl2,    l2h, l2l, HID_DIM, HID_DIM, HID_DIM, HID_DIM);
    split_wt_kernel<<<sgrid1(64 * 512),  256>>>(w_last, wlh, wll, HID_DIM, C_DIM,   HID_DIM, 64);
    split_wt_kernel<<<sgrid1(64 * 512),  256>>>(wl3,    l3h, l3l, HID_DIM, C_DIM,   HID_DIM, 64);
    split_wt_kernel<<<sgrid1(512 * 64),  256>>>(wl0,    l0h, l0l, C_DIM,   HID_DIM, 64,      HID_DIM);
    pad_label_kernel<<<(int)(((size_t)N_DIM * 64 + 255) / 256), 256>>>(label_emb, labp);

    // 1) fused attention -> right [N, F]
    attn_kernel<<<(N_DIM + 3) / 4, 128>>>(features, wa, ba, right);

    auto hgrid = [](int N) { return dim3((unsigned)((N + 63) / 64), (unsigned)((N_DIM + 127) / 128)); };
    const dim3 hblk(256);

    // 2) x1 = right @ w0 + b0                    (K=256)
    hmma_k<0, 1, 0, 0><<<hgrid(HID_DIM), hblk, HM_SMEM>>>(
        right, nullptr, w0h, w0l, b0, nullptr, x1, N_DIM, HID_DIM, F_DIM, nullptr, nullptr);

    // 3) x2 = support(x1, x1) @ wg1 + prelu(x1)
    hmma_k<2, 0, 0, 2><<<hgrid(HID_DIM), hblk, HM_SMEM>>>(
        x1, x1, g1h, g1l, nullptr, x1, x2, N_DIM, HID_DIM, HID_DIM, a_out, a_out);

    // 4) x3 = support(x2, x1) @ wg2 + prelu(x2)
    hmma_k<2, 0, 0, 2><<<hgrid(HID_DIM), hblk, HM_SMEM>>>(
        x2, x1, g2h, g2l, nullptr, x2, x3, N_DIM, HID_DIM, HID_DIM, a_out, a_out);

    // 5) xout = prelu(x3) @ w_last + b_last      (N=47 ragged)
    hmma_k<1, 1, 0, 0><<<hgrid(C_DIM), hblk, HM_SMEM>>>(
        x3, nullptr, wlh, wll, b_last, nullptr, xout, N_DIM, C_DIM, HID_DIM, a_out, nullptr);

    // 6) y0 = prelu(lab_pad @ wl0 + bl0)         (K padded to 64) -> x1
    hmma_k<0, 1, 1, 0><<<hgrid(HID_DIM), hblk, HM_SMEM>>>(
        labp, nullptr, l0h, l0l, bl0, nullptr, x1, N_DIM, HID_DIM, 64, nullptr, a_lab);

    // 7) y1 = prelu(y0 @ wl1 + bl1) -> x2
    hmma_k<0, 1, 1, 0><<<hgrid(HID_DIM), hblk, HM_SMEM>>>(
        x1, nullptr, l1h, l1l, bl1, nullptr, x2, N_DIM, HID_DIM, HID_DIM, nullptr, a_lab);

    // 8) y2 = prelu(y1 @ wl2 + bl2) -> x3
    hmma_k<0, 1, 1, 0><<<hgrid(HID_DIM), hblk, HM_SMEM>>>(
        x2, nullptr, l2h, l2l, bl2, nullptr, x3, N_DIM, HID_DIM, HID_DIM, nullptr, a_lab);

    // 9) out = y2 @ wl3 + bl3 + xout             (N=47 ragged)
    hmma_k<0, 1, 0, 1><<<hgrid(C_DIM), hblk, HM_SMEM>>>(
        x3, nullptr, l3h, l3l, bl3, xout, (float*)d_out, N_DIM, C_DIM, HID_DIM, nullptr, nullptr);
}